// round 13
// baseline (speedup 1.0000x reference)
#include <cuda_runtime.h>
#include <math.h>
#include <stdint.h>

#define S3 0.5773502691896258f
#define S2 0.7071067811865476f
#define EPS 1e-5f

// pre-rounded (tf32 rna) weights: W1[4096] | W2[57344] | Ws[98304] | Wv[65536]
__device__ float g_wr[225280];
#define W1R_OFF 0
#define W2R_OFF 4096
#define WSR_OFF 61440
#define WVR_OFF 159744

__device__ __forceinline__ float tf32r(float x) {
    uint32_t u;
    asm("cvt.rna.tf32.f32 %0, %1;" : "=r"(u) : "f"(x));
    return __uint_as_float(u);
}
// mma.sync m16n8k8 tf32: D += A(16x8) * B(8x8)^T, fp32 accum (baseline PTX, sm_80+)
__device__ __forceinline__ void mma8(float d[4], const uint32_t a[4], const uint32_t b[2]) {
    asm volatile(
        "mma.sync.aligned.m16n8k8.row.col.f32.tf32.tf32.f32 "
        "{%0,%1,%2,%3}, {%4,%5,%6,%7}, {%8,%9}, {%0,%1,%2,%3};"
        : "+f"(d[0]), "+f"(d[1]), "+f"(d[2]), "+f"(d[3])
        : "r"(a[0]), "r"(a[1]), "r"(a[2]), "r"(a[3]), "r"(b[0]), "r"(b[1]));
}
// Packed A tile: quad (mt,ks,lane) = [(r,k),(r,k+4),(r+8,k),(r+8,k+4)],
// r = mt*16 + lane/4, k = ks*8 + lane%4.  One LDS.128 per fragment.
__device__ __forceinline__ void ldApk(uint32_t a[4], const float4* Ap, int mt, int ks, int lane) {
    float4 v = Ap[(mt * 8 + ks) * 32 + lane];
    a[0] = __float_as_uint(v.x);
    a[1] = __float_as_uint(v.z);
    a[2] = __float_as_uint(v.y);
    a[3] = __float_as_uint(v.w);
}
// B fragment from row-major [k][n] tile, stride SB (SB % 32 == 8) -> conflict-free
__device__ __forceinline__ void ldBk(uint32_t b[2], const float* Bs, int SB,
                                     int n0, int k0, int qr, int qc) {
    b[0] = __float_as_uint(Bs[(k0 + qc) * SB + n0 + qr]);
    b[1] = __float_as_uint(Bs[(k0 + qc + 4) * SB + n0 + qr]);
}
__device__ __forceinline__ float quad_sum(float v) {
    v += __shfl_xor_sync(0xffffffffu, v, 1);
    v += __shfl_xor_sync(0xffffffffu, v, 2);
    return v;
}
__device__ __forceinline__ void cpa16(uint32_t saddr, const float* g) {
    asm volatile("cp.async.ca.shared.global [%0], [%1], 16;" :: "r"(saddr), "l"(g));
}
#define CPA_COMMIT() asm volatile("cp.async.commit_group;" ::: "memory")
#define CPA_WAIT0()  asm volatile("cp.async.wait_group 0;" ::: "memory")
#define CPA_WAIT1()  asm volatile("cp.async.wait_group 1;" ::: "memory")
__device__ __forceinline__ uint32_t smem_u32(const void* p) {
    return (uint32_t)__cvta_generic_to_shared(p);
}

// ---------------------------------------------------------------------------
// K0: pre-round weights to tf32 (rna) into g_wr.  225280 elems = 880x256.
// ---------------------------------------------------------------------------
__global__ __launch_bounds__(256) void k0_round(
    const float* __restrict__ W1, const float* __restrict__ W2,
    const float* __restrict__ Ws, const float* __restrict__ Wv)
{
    int i = blockIdx.x * 256 + threadIdx.x;
    float v;
    if (i < 4096)        v = W1[i];
    else if (i < 61440)  v = W2[i - 4096];
    else if (i < 159744) v = Ws[i - 61440];
    else                 v = Wv[i - 159744];
    g_wr[i] = tf32r(v);
}

// ===========================================================================
// H stage: Ah (packed es) -> h = silu(LN(es@W1 + b1)), W1 in Bm (SB=72).
// 512 thr: wm = wid&1, wn = wid>>1 (8 N-cols each).
// ===========================================================================
#define H_STAGE(sm, Ah4, Bm, redS, redQ)                                          \
{                                                                                 \
    float hacc[2][4];                                                             \
    _Pragma("unroll") for (int mt = 0; mt < 2; mt++)                              \
        _Pragma("unroll") for (int f = 0; f < 4; f++) hacc[mt][f] = 0.f;          \
    _Pragma("unroll") for (int ks = 0; ks < 8; ks++) {                            \
        uint32_t a0[4], a1[4], b[2];                                              \
        ldApk(a0, Ah4, wm * 2, ks, lane);                                         \
        ldApk(a1, Ah4, wm * 2 + 1, ks, lane);                                     \
        ldBk(b, Bm, 72, wn * 8, ks * 8, qr, qc);                                  \
        mma8(hacc[0], a0, b);                                                     \
        mma8(hacc[1], a1, b);                                                     \
    }                                                                             \
    __syncthreads();  /* done reading W1 (Bm) and es (Ah) */                      \
    COMMIT_BMAIN(0);                                                              \
    float cb[2], cgl[2], cBl[2];                                                  \
    _Pragma("unroll") for (int c = 0; c < 2; c++) {                               \
        int col = wn * 8 + qc * 2 + c;                                            \
        cb[c] = b1[col]; cgl[c] = lg[col]; cBl[c] = lb[col];                      \
    }                                                                             \
    _Pragma("unroll") for (int mt = 0; mt < 2; mt++)                              \
        _Pragma("unroll") for (int h = 0; h < 2; h++) {                           \
            float s = 0.f, q2 = 0.f;                                              \
            _Pragma("unroll") for (int c = 0; c < 2; c++) {                       \
                float v = hacc[mt][h * 2 + c] + cb[c];                            \
                hacc[mt][h * 2 + c] = v;                                          \
                s += v; q2 += v * v;                                              \
            }                                                                     \
            s = quad_sum(s); q2 = quad_sum(q2);                                   \
            if (qc == 0) {                                                        \
                int r = wm * 32 + mt * 16 + qr + h * 8;                           \
                redS[r * 8 + wn] = s; redQ[r * 8 + wn] = q2;                      \
            }                                                                     \
        }                                                                         \
    __syncthreads();                                                              \
    _Pragma("unroll") for (int mt = 0; mt < 2; mt++)                              \
        _Pragma("unroll") for (int h = 0; h < 2; h++) {                           \
            int r = wm * 32 + mt * 16 + qr + h * 8;                               \
            float s = 0.f, q2 = 0.f;                                              \
            _Pragma("unroll") for (int w8 = 0; w8 < 8; w8++) {                    \
                s += redS[r * 8 + w8]; q2 += redQ[r * 8 + w8];                    \
            }                                                                     \
            float mu = s * (1.f / 64.f);                                          \
            float rstd = rsqrtf(fmaxf(q2 * (1.f / 64.f) - mu * mu, 0.f) + EPS);   \
            int mtp = wm * 2 + mt;                                                \
            _Pragma("unroll") for (int c = 0; c < 2; c++) {                       \
                float v = (hacc[mt][h * 2 + c] - mu) * rstd * cgl[c] + cBl[c];    \
                v = v / (1.f + expf(-v));                                         \
                int col = wn * 8 + qc * 2 + c;                                    \
                int word = ((mtp * 8 + (col >> 3)) * 32 + qr * 4 + (col & 3)) * 4 \
                           + h * 2 + ((col >> 2) & 1);                            \
                sm[word] = tf32r(v);                                              \
            }                                                                     \
        }                                                                         \
    __syncthreads();                                                              \
}

// wMMA stage: w-slice (64 cols, base given) = h @ W2cols + roff -> wsm (s68).
// qn = NEXT chunk's column base (or -1): commits its W2 slice after the sync.
#define W_STAGE(Ah4, W2t, wsm, base, nbn)                                         \
{                                                                                 \
    float wacc[2][4];                                                             \
    _Pragma("unroll") for (int mt = 0; mt < 2; mt++)                              \
        _Pragma("unroll") for (int f = 0; f < 4; f++) wacc[mt][f] = 0.f;          \
    _Pragma("unroll") for (int ks = 0; ks < 8; ks++) {                            \
        uint32_t a0[4], a1[4], b[2];                                              \
        ldApk(a0, Ah4, wm * 2, ks, lane);                                         \
        ldApk(a1, Ah4, wm * 2 + 1, ks, lane);                                     \
        ldBk(b, W2t, 72, wn * 8, ks * 8, qr, qc);                                 \
        mma8(wacc[0], a0, b);                                                     \
        mma8(wacc[1], a1, b);                                                     \
    }                                                                             \
    __syncthreads();  /* done reading W2t */                                      \
    if ((nbn) >= 0) {                                                             \
        for (int s = tid; s < 1024; s += 512) {                                   \
            int k = s >> 4, n4 = s & 15;                                          \
            cpa16(W2U + (uint32_t)(k * 72 + n4 * 4) * 4,                          \
                  g_wr + W2R_OFF + k * 896 + (nbn) + n4 * 4);                     \
        }                                                                         \
        CPA_COMMIT();                                                             \
    }                                                                             \
    _Pragma("unroll") for (int mt = 0; mt < 2; mt++)                              \
        _Pragma("unroll") for (int h = 0; h < 2; h++) {                           \
            int r = wm * 32 + mt * 16 + qr + h * 8;                               \
            _Pragma("unroll") for (int c = 0; c < 2; c++) {                       \
                int u = wn * 8 + qc * 2 + c;                                      \
                wsm[r * 68 + u] = wacc[mt][h * 2 + c] + roff[(base) + u];         \
            }                                                                     \
        }                                                                         \
    __syncthreads();  /* wsm visible */                                           \
}

// ---------------------------------------------------------------------------
// F2: scalar path (fused). 64 edges/block, 512 threads, 1 CTA.
// smem(floats): Ah 0..4095 | As 4096..8191 | Bm 8192..25087 (SB=264)
//   | W2t 25088..29695 (SB=72) | wsm 29696..34047 (s68) | ysm 34048
//   | redS 34304 | redQ 34816 | total 35328  (141 KB -> 87 KB L1D remains)
// ---------------------------------------------------------------------------
#define F2_SMEM (35328 * 4)
__global__ __launch_bounds__(512, 1) void f2_s(
    const float* __restrict__ node, const float* __restrict__ eattr,
    const float* __restrict__ es,
    const float* __restrict__ b1, const float* __restrict__ lg,
    const float* __restrict__ lb, const float* __restrict__ roff,
    const float* __restrict__ bs, const float* __restrict__ gs,
    const float* __restrict__ gb, float* __restrict__ out, int E)
{
    extern __shared__ float sm[];
    float4* Ah4 = (float4*)sm;
    float4* As4 = (float4*)(sm + 4096);
    float*  Bm  = sm + 8192;
    float*  W2t = sm + 25088;
    float*  wsm = sm + 29696;
    float*  ysm = sm + 34048;
    float* redS = sm + 34304;
    float* redQ = sm + 34816;
    const uint32_t BmU = smem_u32(Bm), W2U = smem_u32(W2t);
    const int tid = threadIdx.x, wid = tid >> 5, lane = tid & 31;
    const int qr = lane >> 2, qc = lane & 3;
    const int e0 = blockIdx.x * 64;
    const int wm = wid & 1, wn = wid >> 1;
    const int Q = 6;

#define COMMIT_BMAIN(qq) do {                                                     \
    for (int s = tid; s < 4096; s += 512) {                                       \
        int k = s >> 6, n4 = s & 63;                                              \
        cpa16(BmU + (uint32_t)(k * 264 + n4 * 4) * 4,                             \
              g_wr + WSR_OFF + ((qq) * 64 + k) * 256 + n4 * 4);                   \
    }                                                                             \
    CPA_COMMIT(); } while (0)

    auto colbase = [](int qq) { return (qq < 4) ? qq * 64 : 640 + (qq - 4) * 64; };

    // G1: W1 -> Bm
    for (int s = tid; s < 1024; s += 512) {
        int k = s >> 4, n4 = s & 15;
        cpa16(BmU + (uint32_t)(k * 72 + n4 * 4) * 4, g_wr + W1R_OFF + k * 64 + n4 * 4);
    }
    CPA_COMMIT();
    // G2: W2cols(0) -> W2t
    for (int s = tid; s < 1024; s += 512) {
        int k = s >> 4, n4 = s & 15;
        cpa16(W2U + (uint32_t)(k * 72 + n4 * 4) * 4, g_wr + W2R_OFF + k * 896 + n4 * 4);
    }
    CPA_COMMIT();
    if (tid < 256) {
        int ge = e0 + (tid >> 2);
        ysm[tid] = (ge < E) ? eattr[(size_t)ge * 4 + (tid & 3)] : 0.f;
    }
    for (int qd = tid; qd < 1024; qd += 512) {
        int mt = qd >> 8, kg = (qd >> 5) & 7, ln = qd & 31;
        int ea = e0 + mt * 16 + (ln >> 2), ka = kg * 8 + (ln & 3);
        int eb = ea + 8;
        float v00 = (ea < E) ? es[(size_t)ea * 64 + ka] : 0.f;
        float v01 = (ea < E) ? es[(size_t)ea * 64 + ka + 4] : 0.f;
        float v10 = (eb < E) ? es[(size_t)eb * 64 + ka] : 0.f;
        float v11 = (eb < E) ? es[(size_t)eb * 64 + ka + 4] : 0.f;
        Ah4[qd] = make_float4(tf32r(v00), tf32r(v01), tf32r(v10), tf32r(v11));
    }
    CPA_WAIT1();
    __syncthreads();

    H_STAGE(sm, Ah4, Bm, redS, redQ)

    float acc[2][4][4];
#pragma unroll
    for (int mt = 0; mt < 2; mt++)
#pragma unroll
        for (int nt = 0; nt < 4; nt++)
#pragma unroll
            for (int f = 0; f < 4; f++) acc[mt][nt][f] = 0.f;

    for (int q = 0; q < Q; q++) {
        CPA_WAIT1();          // W2t(q) ready (Bmain(q) may pend)
        __syncthreads();
        {
            int base = colbase(q);
            int nbn = (q + 1 < Q) ? colbase(q + 1) : -1;
            W_STAGE(Ah4, W2t, wsm, base, nbn)
        }
        // build As(q) from node + wsm
        for (int qd = tid; qd < 1024; qd += 512) {
            int mt = qd >> 8, kg = (qd >> 5) & 7, ln = qd & 31;
            int ea = mt * 16 + (ln >> 2), ka = kg * 8 + (ln & 3);
            float v[4];
#pragma unroll
            for (int t = 0; t < 4; t++) {
                int e = ea + (t >> 1) * 8, kk = ka + (t & 1) * 4;
                int ge = e0 + e;
                v[t] = 0.f;
                if (ge < E) {
                    if (q < 4) {
                        v[t] = node[(size_t)ge * 640 + q * 64 + kk] * ysm[e * 4]
                             * wsm[e * 68 + kk];
                    } else {
                        int j = (q - 4) * 64 + kk;
                        const float* xp = node + (size_t)ge * 640 + 256 + 3 * j;
                        float d = xp[0] * ysm[e * 4 + 1] + xp[1] * ysm[e * 4 + 2]
                                + xp[2] * ysm[e * 4 + 3];
                        v[t] = S3 * d * wsm[e * 68 + kk];
                    }
                }
            }
            As4[qd] = make_float4(tf32r(v[0]), tf32r(v[1]), tf32r(v[2]), tf32r(v[3]));
        }
        if (q + 1 < Q) CPA_WAIT1(); else CPA_WAIT0();   // Bmain(q) ready
        __syncthreads();
#pragma unroll
        for (int ks = 0; ks < 8; ks++) {
            uint32_t a0[4], a1[4];
            ldApk(a0, As4, wm * 2, ks, lane);
            ldApk(a1, As4, wm * 2 + 1, ks, lane);
#pragma unroll
            for (int nt = 0; nt < 4; nt++) {
                uint32_t b[2];
                ldBk(b, Bm, 264, wn * 32 + nt * 8, ks * 8, qr, qc);
                mma8(acc[0][nt], a0, b);
                mma8(acc[1][nt], a1, b);
            }
        }
        __syncthreads();
        if (q + 1 < Q) COMMIT_BMAIN(q + 1);
    }

    // epilogue: +bias, LN over 256 cols (cross 8 wn warps), write
    float cbv[8], cgv[8], cBv[8];
#pragma unroll
    for (int nt = 0; nt < 4; nt++)
#pragma unroll
        for (int c = 0; c < 2; c++) {
            int col = wn * 32 + nt * 8 + qc * 2 + c;
            cbv[nt * 2 + c] = bs[col]; cgv[nt * 2 + c] = gs[col]; cBv[nt * 2 + c] = gb[col];
        }
#pragma unroll
    for (int mt = 0; mt < 2; mt++)
#pragma unroll
        for (int h = 0; h < 2; h++) {
            float s = 0.f, q2 = 0.f;
#pragma unroll
            for (int nt = 0; nt < 4; nt++)
#pragma unroll
                for (int c = 0; c < 2; c++) {
                    float v = acc[mt][nt][h * 2 + c] + cbv[nt * 2 + c];
                    acc[mt][nt][h * 2 + c] = v;
                    s += v; q2 += v * v;
                }
            s = quad_sum(s); q2 = quad_sum(q2);
            if (qc == 0) {
                int r = wm * 32 + mt * 16 + qr + h * 8;
                redS[r * 8 + wn] = s; redQ[r * 8 + wn] = q2;
            }
        }
    __syncthreads();
#pragma unroll
    for (int mt = 0; mt < 2; mt++)
#pragma unroll
        for (int h = 0; h < 2; h++) {
            int r = wm * 32 + mt * 16 + qr + h * 8, ge = e0 + r;
            float s = 0.f, q2 = 0.f;
#pragma unroll
            for (int w8 = 0; w8 < 8; w8++) { s += redS[r * 8 + w8]; q2 += redQ[r * 8 + w8]; }
            float mu = s * (1.f / 256.f);
            float rstd = rsqrtf(fmaxf(q2 * (1.f / 256.f) - mu * mu, 0.f) + EPS);
            if (ge < E) {
#pragma unroll
                for (int nt = 0; nt < 4; nt++) {
                    int col = wn * 32 + nt * 8 + qc * 2;
                    float2 v;
                    v.x = (acc[mt][nt][h * 2] - mu) * rstd * cgv[nt * 2] + cBv[nt * 2];
                    v.y = (acc[mt][nt][h * 2 + 1] - mu) * rstd * cgv[nt * 2 + 1] + cBv[nt * 2 + 1];
                    *(float2*)&out[(size_t)ge * 640 + col] = v;
                }
            }
        }
#undef COMMIT_BMAIN
}

// ---------------------------------------------------------------------------
// F3: vector path (fused), 4-plane formulation. 64 edges/block, 512 threads.
// Chunk order QL = {0,1,2,3, 4,6, 5,7}: chunk 6 re-reads chunk 4's x1 tile
// (48 KB) and 7 re-reads 5's, back-to-back -> L1-hot (87 KB L1D available).
// smem(floats): Ah 0 | A0 4096 | A1 8192 | A2 12288 | Bm 16384..25087 (SB=136)
//   | W2t 25088 (SB=72) | wsm 29696 (s68) | ysm 34048 | redS 34304
//   | redQ 34816 | total 35328
// ---------------------------------------------------------------------------
#define F3_SMEM (35328 * 4)
__global__ __launch_bounds__(512, 1) void f3_v(
    const float* __restrict__ node, const float* __restrict__ eattr,
    const float* __restrict__ es,
    const float* __restrict__ b1, const float* __restrict__ lg,
    const float* __restrict__ lb, const float* __restrict__ roff,
    const float* __restrict__ gv, float* __restrict__ out, int E)
{
    extern __shared__ float sm[];
    float4* Ah4 = (float4*)sm;
    float4* A04 = (float4*)(sm + 4096);
    float4* A14 = (float4*)(sm + 8192);
    float4* A24 = (float4*)(sm + 12288);
    float*  Bm  = sm + 16384;
    float*  W2t = sm + 25088;
    float*  wsm = sm + 29696;
    float*  ysm = sm + 34048;
    float* redS = sm + 34304;
    float* redQ = sm + 34816;
    const uint32_t BmU = smem_u32(Bm), W2U = smem_u32(W2t);
    const int tid = threadIdx.x, wid = tid >> 5, lane = tid & 31;
    const int qr = lane >> 2, qc = lane & 3;
    const int e0 = blockIdx.x * 64;
    const int wm = wid & 1, wn = wid >> 1;
    const int n0 = wn * 16;
    const int Q = 8;
    // chunk schedule: parts b/c interleaved for x1-tile L1 reuse
    const int QL[8] = {0, 1, 2, 3, 4, 6, 5, 7};

#define COMMIT_BMAIN(qq) do {                                                     \
    for (int s = tid; s < 2048; s += 512) {                                       \
        int k = s >> 5, n4 = s & 31;                                              \
        cpa16(BmU + (uint32_t)(k * 136 + n4 * 4) * 4,                             \
              g_wr + WVR_OFF + ((qq) * 64 + k) * 128 + n4 * 4);                   \
    }                                                                             \
    CPA_COMMIT(); } while (0)

    auto colbase = [](int qq) {
        return (qq < 4) ? 256 + qq * 64 : (qq < 6 ? 512 + (qq - 4) * 64
                                                  : 768 + (qq - 6) * 64);
    };

    // G1: W1 -> Bm
    for (int s = tid; s < 1024; s += 512) {
        int k = s >> 4, n4 = s & 15;
        cpa16(BmU + (uint32_t)(k * 72 + n4 * 4) * 4, g_wr + W1R_OFF + k * 64 + n4 * 4);
    }
    CPA_COMMIT();
    // G2: W2cols(QL[0]=0) = wB cols 256.. -> W2t
    for (int s = tid; s < 1024; s += 512) {
        int k = s >> 4, n4 = s & 15;
        cpa16(W2U + (uint32_t)(k * 72 + n4 * 4) * 4, g_wr + W2R_OFF + k * 896 + 256 + n4 * 4);
    }
    CPA_COMMIT();
    if (tid < 256) {
        int ge = e0 + (tid >> 2);
        ysm[tid] = (ge < E) ? eattr[(size_t)ge * 4 + (tid & 3)] : 0.f;
    }
    for (int qd = tid; qd < 1024; qd += 512) {
        int mt = qd >> 8, kg = (qd >> 5) & 7, ln = qd & 31;
        int ea = e0 + mt * 16 + (ln >> 2), ka = kg * 8 + (ln & 3);
        int eb = ea + 8;
        float v00 = (ea < E) ? es[(size_t)ea * 64 + ka] : 0.f;
        float v01 = (ea < E) ? es[(size_t)ea * 64 + ka + 4] : 0.f;
        float v10 = (eb < E) ? es[(size_t)eb * 64 + ka] : 0.f;
        float v11 = (eb < E) ? es[(size_t)eb * 64 + ka + 4] : 0.f;
        Ah4[qd] = make_float4(tf32r(v00), tf32r(v01), tf32r(v10), tf32r(v11));
    }
    CPA_WAIT1();
    __syncthreads();

    H_STAGE(sm, Ah4, Bm, redS, redQ)   // COMMIT_BMAIN(0) fires inside (QL[0]=0)

    float accR[2][2][4];
    float accM[3][2][2][4];
#pragma unroll
    for (int mt = 0; mt < 2; mt++)
#pragma unroll
        for (int nt = 0; nt < 2; nt++)
#pragma unroll
            for (int f = 0; f < 4; f++) {
                accR[mt][nt][f] = 0.f;
#pragma unroll
                for (int m = 0; m < 3; m++) accM[m][mt][nt][f] = 0.f;
            }

    for (int qi = 0; qi < Q; qi++) {
        const int q = QL[qi];
        CPA_WAIT1();
        __syncthreads();
        {
            int base = colbase(q);
            int nbn = (qi + 1 < Q) ? colbase(QL[qi + 1]) : -1;
            W_STAGE(Ah4, W2t, wsm, base, nbn)
        }
        // build A planes (addresses keyed on actual q)
        if (q < 4) {
            for (int qd = tid; qd < 1024; qd += 512) {
                int mt = qd >> 8, kg = (qd >> 5) & 7, ln = qd & 31;
                int ea = mt * 16 + (ln >> 2), ka = kg * 8 + (ln & 3);
                float v[4];
#pragma unroll
                for (int t = 0; t < 4; t++) {
                    int e = ea + (t >> 1) * 8, kk = ka + (t & 1) * 4;
                    int ge = e0 + e;
                    v[t] = (ge < E)
                         ? node[(size_t)ge * 640 + q * 64 + kk] * wsm[e * 68 + kk]
                         : 0.f;
                }
                A04[qd] = make_float4(tf32r(v[0]), tf32r(v[1]), tf32r(v[2]), tf32r(v[3]));
            }
        } else {
            for (int qd = tid; qd < 1024; qd += 512) {
                int mt = qd >> 8, kg = (qd >> 5) & 7, ln = qd & 31;
                int ea = mt * 16 + (ln >> 2), ka = kg * 8 + (ln & 3);
                float a0[4], a1[4], a2[4];
#pragma unroll
                for (int t = 0; t < 4; t++) {
                    int e = ea + (t >> 1) * 8, kk = ka + (t & 1) * 4;
                    int ge = e0 + e;
                    a0[t] = a1[t] = a2[t] = 0.f;
                    if (ge < E) {
                        if (q < 6) {
                            int j = (q - 4) * 64 + kk;
                            const float* xp = node + (size_t)ge * 640 + 256 + 3 * j;
                            float f = ysm[e * 4] * wsm[e * 68 + kk];
                            a0[t] = xp[0] * f; a1[t] = xp[1] * f; a2[t] = xp[2] * f;
                        } else {
                            int j = (q - 6) * 64 + kk;
                            const float* xp = node + (size_t)ge * 640 + 256 + 3 * j;
                            float x0v = xp[0], x1v = xp[1], x2v = xp[2];
                            float z0 = ysm[e * 4 + 1], z1 = ysm[e * 4 + 2], z2 = ysm[e * 4 + 3];
                            float f = S2 * wsm[e * 68 + kk];
                            a0[t] = (x1v * z2 - x2v * z1) * f;
                            a1[t] = (x2v * z0 - x0v * z2) * f;
                            a2[t] = (x0v * z1 - x1v * z0) * f;
                        }
                    }
                }
                A04[qd] = make_float4(tf32r(a0[0]), tf32r(a0[1]), tf32r(a0[2]), tf32r(a0[3]));
                A14[qd] = make_float4(tf32r(a1[0]), tf32r(a1[1]), tf32r(a1[2]), tf32r(a1[3]));
                A24[qd] = make_float4(tf32r(a2[0]), tf32r(a2[1]), tf32r(a2[2]), tf32r(a2[3]));
            }
        }
        if (qi + 1 < Q) CPA_WAIT1(); else CPA_WAIT0();
        __syncthreads();
        if (q < 4) {
#pragma unroll
            for (int ks = 0; ks < 8; ks++) {
                uint32_t a0[4], a1[4];
                ldApk(a0, A04, wm * 2, ks, lane);
                ldApk(a1, A04, wm * 2 + 1, ks, lane);
#pragma unroll
                for (int nt = 0; nt < 2; nt++) {
                    uint32_t b[2];
                    ldBk(b, Bm, 136, n0 + nt * 8, ks * 8, qr, qc);
                    mma8(accR[0][nt], a0, b);
                    mma8(accR[1][nt], a1, b);
                }
            }
        } else {
#pragma unroll
            for (int ks = 0; ks < 8; ks++) {
                uint32_t b[2][2];
#pragma unroll
                for (int nt = 0; nt < 2; nt++) ldBk(b[nt], Bm, 136, n0 + nt * 8, ks * 8, qr, qc);
                const float4* Ap[3] = {A04, A14, A24};
#pragma unroll
                for (int m = 0; m < 3; m++) {
                    uint32_t a0[4], a1[4];
                    ldApk(a0, Ap[m], wm * 2, ks, lane);
                    ldApk(a1, Ap[m], wm * 2 + 1, ks, lane);
#pragma unroll
                    for (int nt = 0; nt < 2; nt++) {
                        mma8(accM[m][0][nt], a0, b[nt]);
                        mma8(accM[m][1][nt], a1, b[nt]);
                    }
                }
            }
        }
        __syncthreads();
        if (qi + 1 < Q) COMMIT_BMAIN(QL[qi + 1]);
    }

    // epilogue: fold R plane, sumsq, norm, write
#pragma unroll
    for (int mt = 0; mt < 2; mt++)
#pragma unroll
        for (int h = 0; h < 2; h++) {
            int e = wm * 32 + mt * 16 + qr + h * 8;
            float z0 = ysm[e * 4 + 1], z1 = ysm[e * 4 + 2], z2 = ysm[e * 4 + 3];
            float s = 0.f;
#pragma unroll
            for (int nt = 0; nt < 2; nt++)
#pragma unroll
                for (int c = 0; c < 2; c++) {
                    float R = accR[mt][nt][h * 2 + c];
                    float v0 = z0 * R + accM[0][mt][nt][h * 2 + c];
                    float v1 = z1 * R + accM[1][mt][nt][h * 2 + c];
                    float v2 = z2 * R + accM[2][mt][nt][h * 2 + c];
                    accM[0][mt][nt][h * 2 + c] = v0;
                    accM[1][mt][nt][h * 2 + c] = v1;
                    accM[2][mt][nt][h * 2 + c] = v2;
                    s += v0 * v0 + v1 * v1 + v2 * v2;
                }
            s = quad_sum(s);
            if (qc == 0) redQ[e * 8 + wn] = s;
        }
    __syncthreads();
    float cg[4];
#pragma unroll
    for (int nt = 0; nt < 2; nt++)
#pragma unroll
        for (int c = 0; c < 2; c++) cg[nt * 2 + c] = gv[n0 + nt * 8 + qc * 2 + c];
#pragma unroll
    for (int mt = 0; mt < 2; mt++)
#pragma unroll
        for (int h = 0; h < 2; h++) {
            int e = wm * 32 + mt * 16 + qr + h * 8, ge = e0 + e;
            float qt = 0.f;
#pragma unroll
            for (int w8 = 0; w8 < 8; w8++) qt += redQ[e * 8 + w8];
            float rstd = rsqrtf(qt * (1.f / 384.f) + EPS);
            if (ge < E) {
                float* ob = out + (size_t)ge * 640 + 256;
#pragma unroll
                for (int nt = 0; nt < 2; nt++)
#pragma unroll
                    for (int c = 0; c < 2; c++) {
                        int col = n0 + nt * 8 + qc * 2 + c;
                        float g = cg[nt * 2 + c] * rstd;
                        ob[3 * col + 0] = accM[0][mt][nt][h * 2 + c] * g;
                        ob[3 * col + 1] = accM[1][mt][nt][h * 2 + c] * g;
                        ob[3 * col + 2] = accM[2][mt][nt][h * 2 + c] * g;
                    }
            }
        }
#undef COMMIT_BMAIN
}

// ---------------------------------------------------------------------------
extern "C" void kernel_launch(void* const* d_in, const int* in_sizes, int n_in,
                              void* d_out, int out_size)
{
    const float* node  = (const float*)d_in[0];   // (E, 640)
    const float* eattr = (const float*)d_in[1];   // (E, 4)
    const float* escal = (const float*)d_in[2];   // (E, 64)
    const float* rW1   = (const float*)d_in[3];   // (64, 64)
    const float* rb1   = (const float*)d_in[4];   // (64,)
    const float* rlg   = (const float*)d_in[5];   // (64,)
    const float* rlb   = (const float*)d_in[6];   // (64,)
    const float* rW2   = (const float*)d_in[7];   // (64, 896)
    const float* roff  = (const float*)d_in[8];   // (896,)
    const float* Ws    = (const float*)d_in[9];   // (384, 256)
    const float* bs    = (const float*)d_in[10];  // (256,)
    const float* Wv    = (const float*)d_in[11];  // (512, 128)
    const float* gs    = (const float*)d_in[12];  // (256,)
    const float* gb    = (const float*)d_in[13];  // (256,)
    const float* gv    = (const float*)d_in[14];  // (128,)
    float* out = (float*)d_out;

    const int E = in_sizes[1] / 4;
    const int nb64 = (E + 63) / 64;

    cudaFuncSetAttribute(f2_s, cudaFuncAttributeMaxDynamicSharedMemorySize, F2_SMEM);
    cudaFuncSetAttribute(f3_v, cudaFuncAttributeMaxDynamicSharedMemorySize, F3_SMEM);

    k0_round<<<880, 256>>>(rW1, rW2, Ws, Wv);
    f2_s<<<nb64, 512, F2_SMEM>>>(node, eattr, escal, rb1, rlg, rlb, roff,
                                 bs, gs, gb, out, E);
    f3_v<<<nb64, 512, F3_SMEM>>>(node, eattr, escal, rb1, rlg, rlb, roff,
                                 gv, out, E);
}

// round 14
// speedup vs baseline: 1.0813x; 1.0813x over previous
#include <cuda_runtime.h>
#include <math.h>
#include <stdint.h>

#define S3 0.5773502691896258f
#define S2 0.7071067811865476f
#define EPS 1e-5f

// pre-rounded (tf32 rna) weights: W1[4096] | W2[57344] | Ws[98304] | Wv[65536]
__device__ float g_wr[225280];
#define W1R_OFF 0
#define W2R_OFF 4096
#define WSR_OFF 61440
#define WVR_OFF 159744

__device__ __forceinline__ float tf32r(float x) {
    uint32_t u;
    asm("cvt.rna.tf32.f32 %0, %1;" : "=r"(u) : "f"(x));
    return __uint_as_float(u);
}
// mma.sync m16n8k8 tf32: D += A(16x8) * B(8x8)^T, fp32 accum (baseline PTX, sm_80+)
__device__ __forceinline__ void mma8(float d[4], const uint32_t a[4], const uint32_t b[2]) {
    asm volatile(
        "mma.sync.aligned.m16n8k8.row.col.f32.tf32.tf32.f32 "
        "{%0,%1,%2,%3}, {%4,%5,%6,%7}, {%8,%9}, {%0,%1,%2,%3};"
        : "+f"(d[0]), "+f"(d[1]), "+f"(d[2]), "+f"(d[3])
        : "r"(a[0]), "r"(a[1]), "r"(a[2]), "r"(a[3]), "r"(b[0]), "r"(b[1]));
}
// Packed A tile: quad (mt,ks,lane) = [(r,k),(r,k+4),(r+8,k),(r+8,k+4)],
// r = mt*16 + lane/4, k = ks*8 + lane%4.  One LDS.128 per fragment.
__device__ __forceinline__ void ldApk(uint32_t a[4], const float4* Ap, int mt, int ks, int lane) {
    float4 v = Ap[(mt * 8 + ks) * 32 + lane];
    a[0] = __float_as_uint(v.x);
    a[1] = __float_as_uint(v.z);
    a[2] = __float_as_uint(v.y);
    a[3] = __float_as_uint(v.w);
}
// B fragment from row-major [k][n] tile, stride SB (SB % 32 == 8) -> conflict-free
__device__ __forceinline__ void ldBk(uint32_t b[2], const float* Bs, int SB,
                                     int n0, int k0, int qr, int qc) {
    b[0] = __float_as_uint(Bs[(k0 + qc) * SB + n0 + qr]);
    b[1] = __float_as_uint(Bs[(k0 + qc + 4) * SB + n0 + qr]);
}
__device__ __forceinline__ float quad_sum(float v) {
    v += __shfl_xor_sync(0xffffffffu, v, 1);
    v += __shfl_xor_sync(0xffffffffu, v, 2);
    return v;
}
__device__ __forceinline__ void cpa16(uint32_t saddr, const float* g) {
    asm volatile("cp.async.ca.shared.global [%0], [%1], 16;" :: "r"(saddr), "l"(g));
}
#define CPA_COMMIT() asm volatile("cp.async.commit_group;" ::: "memory")
#define CPA_WAIT0()  asm volatile("cp.async.wait_group 0;" ::: "memory")
#define CPA_WAIT1()  asm volatile("cp.async.wait_group 1;" ::: "memory")
__device__ __forceinline__ uint32_t smem_u32(const void* p) {
    return (uint32_t)__cvta_generic_to_shared(p);
}

// ---------------------------------------------------------------------------
// K0: pre-round weights to tf32 (rna) into g_wr.  225280 elems = 880x256.
// ---------------------------------------------------------------------------
__global__ __launch_bounds__(256) void k0_round(
    const float* __restrict__ W1, const float* __restrict__ W2,
    const float* __restrict__ Ws, const float* __restrict__ Wv)
{
    int i = blockIdx.x * 256 + threadIdx.x;
    float v;
    if (i < 4096)        v = W1[i];
    else if (i < 61440)  v = W2[i - 4096];
    else if (i < 159744) v = Ws[i - 61440];
    else                 v = Wv[i - 159744];
    g_wr[i] = tf32r(v);
}

// ===========================================================================
// H stage: Ah (packed es) -> h = silu(LN(es@W1 + b1)), W1 in Bm (SB=72).
// 512 thr: wm = wid&1, wn = wid>>1 (8 N-cols each).
// ===========================================================================
#define H_STAGE(sm, Ah4, Bm, redS, redQ)                                          \
{                                                                                 \
    float hacc[2][4];                                                             \
    _Pragma("unroll") for (int mt = 0; mt < 2; mt++)                              \
        _Pragma("unroll") for (int f = 0; f < 4; f++) hacc[mt][f] = 0.f;          \
    _Pragma("unroll") for (int ks = 0; ks < 8; ks++) {                            \
        uint32_t a0[4], a1[4], b[2];                                              \
        ldApk(a0, Ah4, wm * 2, ks, lane);                                         \
        ldApk(a1, Ah4, wm * 2 + 1, ks, lane);                                     \
        ldBk(b, Bm, 72, wn * 8, ks * 8, qr, qc);                                  \
        mma8(hacc[0], a0, b);                                                     \
        mma8(hacc[1], a1, b);                                                     \
    }                                                                             \
    __syncthreads();  /* done reading W1 (Bm) and es (Ah) */                      \
    COMMIT_BMAIN(0);                                                              \
    float cb[2], cgl[2], cBl[2];                                                  \
    _Pragma("unroll") for (int c = 0; c < 2; c++) {                               \
        int col = wn * 8 + qc * 2 + c;                                            \
        cb[c] = b1[col]; cgl[c] = lg[col]; cBl[c] = lb[col];                      \
    }                                                                             \
    _Pragma("unroll") for (int mt = 0; mt < 2; mt++)                              \
        _Pragma("unroll") for (int h = 0; h < 2; h++) {                           \
            float s = 0.f, q2 = 0.f;                                              \
            _Pragma("unroll") for (int c = 0; c < 2; c++) {                       \
                float v = hacc[mt][h * 2 + c] + cb[c];                            \
                hacc[mt][h * 2 + c] = v;                                          \
                s += v; q2 += v * v;                                              \
            }                                                                     \
            s = quad_sum(s); q2 = quad_sum(q2);                                   \
            if (qc == 0) {                                                        \
                int r = wm * 32 + mt * 16 + qr + h * 8;                           \
                redS[r * 8 + wn] = s; redQ[r * 8 + wn] = q2;                      \
            }                                                                     \
        }                                                                         \
    __syncthreads();                                                              \
    _Pragma("unroll") for (int mt = 0; mt < 2; mt++)                              \
        _Pragma("unroll") for (int h = 0; h < 2; h++) {                           \
            int r = wm * 32 + mt * 16 + qr + h * 8;                               \
            float s = 0.f, q2 = 0.f;                                              \
            _Pragma("unroll") for (int w8 = 0; w8 < 8; w8++) {                    \
                s += redS[r * 8 + w8]; q2 += redQ[r * 8 + w8];                    \
            }                                                                     \
            float mu = s * (1.f / 64.f);                                          \
            float rstd = rsqrtf(fmaxf(q2 * (1.f / 64.f) - mu * mu, 0.f) + EPS);   \
            int mtp = wm * 2 + mt;                                                \
            _Pragma("unroll") for (int c = 0; c < 2; c++) {                       \
                float v = (hacc[mt][h * 2 + c] - mu) * rstd * cgl[c] + cBl[c];    \
                v = v / (1.f + expf(-v));                                         \
                int col = wn * 8 + qc * 2 + c;                                    \
                int word = ((mtp * 8 + (col >> 3)) * 32 + qr * 4 + (col & 3)) * 4 \
                           + h * 2 + ((col >> 2) & 1);                            \
                sm[word] = tf32r(v);                                              \
            }                                                                     \
        }                                                                         \
    __syncthreads();                                                              \
}

// wMMA stage (merged-barrier version): w-slice (64 cols) = h @ W2cols + roff.
// wsm stores issue BEFORE the single barrier (prev chunk's wsm readers are two
// barriers back, so no concurrent reader); the W2(next) commit issues after it
// (all warps' W2t reads complete).  ONE __syncthreads instead of two.
#define W_STAGE(Ah4, W2t, wsm, base, nbn)                                         \
{                                                                                 \
    float wacc[2][4];                                                             \
    _Pragma("unroll") for (int mt = 0; mt < 2; mt++)                              \
        _Pragma("unroll") for (int f = 0; f < 4; f++) wacc[mt][f] = 0.f;          \
    _Pragma("unroll") for (int ks = 0; ks < 8; ks++) {                            \
        uint32_t a0[4], a1[4], b[2];                                              \
        ldApk(a0, Ah4, wm * 2, ks, lane);                                         \
        ldApk(a1, Ah4, wm * 2 + 1, ks, lane);                                     \
        ldBk(b, W2t, 72, wn * 8, ks * 8, qr, qc);                                 \
        mma8(wacc[0], a0, b);                                                     \
        mma8(wacc[1], a1, b);                                                     \
    }                                                                             \
    _Pragma("unroll") for (int mt = 0; mt < 2; mt++)                              \
        _Pragma("unroll") for (int h = 0; h < 2; h++) {                           \
            int r = wm * 32 + mt * 16 + qr + h * 8;                               \
            _Pragma("unroll") for (int c = 0; c < 2; c++) {                       \
                int u = wn * 8 + qc * 2 + c;                                      \
                wsm[r * 68 + u] = wacc[mt][h * 2 + c] + roff[(base) + u];         \
            }                                                                     \
        }                                                                         \
    __syncthreads();  /* W2t reads done AND wsm visible */                        \
    if ((nbn) >= 0) {                                                             \
        for (int s = tid; s < 1024; s += 512) {                                   \
            int k = s >> 4, n4 = s & 15;                                          \
            cpa16(W2U + (uint32_t)(k * 72 + n4 * 4) * 4,                          \
                  g_wr + W2R_OFF + k * 896 + (nbn) + n4 * 4);                     \
        }                                                                         \
        CPA_COMMIT();                                                             \
    }                                                                             \
}

// ---------------------------------------------------------------------------
// F2: scalar path (fused). 64 edges/block, 512 threads, 1 CTA.
// smem(floats): Ah 0..4095 | As 4096..8191 | Bm 8192..25087 (SB=264)
//   | W2t 25088..29695 (SB=72) | wsm 29696..34047 (s68) | ysm 34048
//   | redS 34304 | redQ 34816 | total 35328  (141 KB)
// ---------------------------------------------------------------------------
#define F2_SMEM (35328 * 4)
__global__ __launch_bounds__(512, 1) void f2_s(
    const float* __restrict__ node, const float* __restrict__ eattr,
    const float* __restrict__ es,
    const float* __restrict__ b1, const float* __restrict__ lg,
    const float* __restrict__ lb, const float* __restrict__ roff,
    const float* __restrict__ bs, const float* __restrict__ gs,
    const float* __restrict__ gb, float* __restrict__ out, int E)
{
    extern __shared__ float sm[];
    float4* Ah4 = (float4*)sm;
    float4* As4 = (float4*)(sm + 4096);
    float*  Bm  = sm + 8192;
    float*  W2t = sm + 25088;
    float*  wsm = sm + 29696;
    float*  ysm = sm + 34048;
    float* redS = sm + 34304;
    float* redQ = sm + 34816;
    const uint32_t BmU = smem_u32(Bm), W2U = smem_u32(W2t);
    const int tid = threadIdx.x, wid = tid >> 5, lane = tid & 31;
    const int qr = lane >> 2, qc = lane & 3;
    const int e0 = blockIdx.x * 64;
    const int wm = wid & 1, wn = wid >> 1;
    const int Q = 6;

#define COMMIT_BMAIN(qq) do {                                                     \
    for (int s = tid; s < 4096; s += 512) {                                       \
        int k = s >> 6, n4 = s & 63;                                              \
        cpa16(BmU + (uint32_t)(k * 264 + n4 * 4) * 4,                             \
              g_wr + WSR_OFF + ((qq) * 64 + k) * 256 + n4 * 4);                   \
    }                                                                             \
    CPA_COMMIT(); } while (0)

    auto colbase = [](int qq) { return (qq < 4) ? qq * 64 : 640 + (qq - 4) * 64; };

    // G1: W1 -> Bm
    for (int s = tid; s < 1024; s += 512) {
        int k = s >> 4, n4 = s & 15;
        cpa16(BmU + (uint32_t)(k * 72 + n4 * 4) * 4, g_wr + W1R_OFF + k * 64 + n4 * 4);
    }
    CPA_COMMIT();
    // G2: W2cols(0) -> W2t
    for (int s = tid; s < 1024; s += 512) {
        int k = s >> 4, n4 = s & 15;
        cpa16(W2U + (uint32_t)(k * 72 + n4 * 4) * 4, g_wr + W2R_OFF + k * 896 + n4 * 4);
    }
    CPA_COMMIT();
    if (tid < 256) {
        int ge = e0 + (tid >> 2);
        ysm[tid] = (ge < E) ? eattr[(size_t)ge * 4 + (tid & 3)] : 0.f;
    }
    for (int qd = tid; qd < 1024; qd += 512) {
        int mt = qd >> 8, kg = (qd >> 5) & 7, ln = qd & 31;
        int ea = e0 + mt * 16 + (ln >> 2), ka = kg * 8 + (ln & 3);
        int eb = ea + 8;
        float v00 = (ea < E) ? es[(size_t)ea * 64 + ka] : 0.f;
        float v01 = (ea < E) ? es[(size_t)ea * 64 + ka + 4] : 0.f;
        float v10 = (eb < E) ? es[(size_t)eb * 64 + ka] : 0.f;
        float v11 = (eb < E) ? es[(size_t)eb * 64 + ka + 4] : 0.f;
        Ah4[qd] = make_float4(tf32r(v00), tf32r(v01), tf32r(v10), tf32r(v11));
    }
    CPA_WAIT1();
    __syncthreads();

    H_STAGE(sm, Ah4, Bm, redS, redQ)

    float acc[2][4][4];
#pragma unroll
    for (int mt = 0; mt < 2; mt++)
#pragma unroll
        for (int nt = 0; nt < 4; nt++)
#pragma unroll
            for (int f = 0; f < 4; f++) acc[mt][nt][f] = 0.f;

    for (int q = 0; q < Q; q++) {
        CPA_WAIT1();          // W2t(q) ready (Bmain(q) may pend)
        __syncthreads();
        {
            int base = colbase(q);
            int nbn = (q + 1 < Q) ? colbase(q + 1) : -1;
            W_STAGE(Ah4, W2t, wsm, base, nbn)
        }
        // build As(q) from node + wsm
        for (int qd = tid; qd < 1024; qd += 512) {
            int mt = qd >> 8, kg = (qd >> 5) & 7, ln = qd & 31;
            int ea = mt * 16 + (ln >> 2), ka = kg * 8 + (ln & 3);
            float v[4];
#pragma unroll
            for (int t = 0; t < 4; t++) {
                int e = ea + (t >> 1) * 8, kk = ka + (t & 1) * 4;
                int ge = e0 + e;
                v[t] = 0.f;
                if (ge < E) {
                    if (q < 4) {
                        v[t] = node[(size_t)ge * 640 + q * 64 + kk] * ysm[e * 4]
                             * wsm[e * 68 + kk];
                    } else {
                        int j = (q - 4) * 64 + kk;
                        const float* xp = node + (size_t)ge * 640 + 256 + 3 * j;
                        float d = xp[0] * ysm[e * 4 + 1] + xp[1] * ysm[e * 4 + 2]
                                + xp[2] * ysm[e * 4 + 3];
                        v[t] = S3 * d * wsm[e * 68 + kk];
                    }
                }
            }
            As4[qd] = make_float4(tf32r(v[0]), tf32r(v[1]), tf32r(v[2]), tf32r(v[3]));
        }
        if (q + 1 < Q) CPA_WAIT1(); else CPA_WAIT0();   // Bmain(q) ready
        __syncthreads();
#pragma unroll
        for (int ks = 0; ks < 8; ks++) {
            uint32_t a0[4], a1[4];
            ldApk(a0, As4, wm * 2, ks, lane);
            ldApk(a1, As4, wm * 2 + 1, ks, lane);
#pragma unroll
            for (int nt = 0; nt < 4; nt++) {
                uint32_t b[2];
                ldBk(b, Bm, 264, wn * 32 + nt * 8, ks * 8, qr, qc);
                mma8(acc[0][nt], a0, b);
                mma8(acc[1][nt], a1, b);
            }
        }
        __syncthreads();
        if (q + 1 < Q) COMMIT_BMAIN(q + 1);
    }

    // epilogue: +bias, LN over 256 cols (cross 8 wn warps), write
    float cbv[8], cgv[8], cBv[8];
#pragma unroll
    for (int nt = 0; nt < 4; nt++)
#pragma unroll
        for (int c = 0; c < 2; c++) {
            int col = wn * 32 + nt * 8 + qc * 2 + c;
            cbv[nt * 2 + c] = bs[col]; cgv[nt * 2 + c] = gs[col]; cBv[nt * 2 + c] = gb[col];
        }
#pragma unroll
    for (int mt = 0; mt < 2; mt++)
#pragma unroll
        for (int h = 0; h < 2; h++) {
            float s = 0.f, q2 = 0.f;
#pragma unroll
            for (int nt = 0; nt < 4; nt++)
#pragma unroll
                for (int c = 0; c < 2; c++) {
                    float v = acc[mt][nt][h * 2 + c] + cbv[nt * 2 + c];
                    acc[mt][nt][h * 2 + c] = v;
                    s += v; q2 += v * v;
                }
            s = quad_sum(s); q2 = quad_sum(q2);
            if (qc == 0) {
                int r = wm * 32 + mt * 16 + qr + h * 8;
                redS[r * 8 + wn] = s; redQ[r * 8 + wn] = q2;
            }
        }
    __syncthreads();
#pragma unroll
    for (int mt = 0; mt < 2; mt++)
#pragma unroll
        for (int h = 0; h < 2; h++) {
            int r = wm * 32 + mt * 16 + qr + h * 8, ge = e0 + r;
            float s = 0.f, q2 = 0.f;
#pragma unroll
            for (int w8 = 0; w8 < 8; w8++) { s += redS[r * 8 + w8]; q2 += redQ[r * 8 + w8]; }
            float mu = s * (1.f / 256.f);
            float rstd = rsqrtf(fmaxf(q2 * (1.f / 256.f) - mu * mu, 0.f) + EPS);
            if (ge < E) {
#pragma unroll
                for (int nt = 0; nt < 4; nt++) {
                    int col = wn * 32 + nt * 8 + qc * 2;
                    float2 v;
                    v.x = (acc[mt][nt][h * 2] - mu) * rstd * cgv[nt * 2] + cBv[nt * 2];
                    v.y = (acc[mt][nt][h * 2 + 1] - mu) * rstd * cgv[nt * 2 + 1] + cBv[nt * 2 + 1];
                    *(float2*)&out[(size_t)ge * 640 + col] = v;
                }
            }
        }
#undef COMMIT_BMAIN
}

// ---------------------------------------------------------------------------
// F3: vector path (fused), 4-plane formulation. 64 edges/block, 512 threads.
// smem(floats): Ah 0 | A0 4096 | A1 8192 | A2 12288 | Bm 16384..25087 (SB=136)
//   | W2t 25088 (SB=72) | wsm 29696 (s68) | ysm 34048 | redS 34304
//   | redQ 34816 | total 35328  (141 KB)
// ---------------------------------------------------------------------------
#define F3_SMEM (35328 * 4)
__global__ __launch_bounds__(512, 1) void f3_v(
    const float* __restrict__ node, const float* __restrict__ eattr,
    const float* __restrict__ es,
    const float* __restrict__ b1, const float* __restrict__ lg,
    const float* __restrict__ lb, const float* __restrict__ roff,
    const float* __restrict__ gv, float* __restrict__ out, int E)
{
    extern __shared__ float sm[];
    float4* Ah4 = (float4*)sm;
    float4* A04 = (float4*)(sm + 4096);
    float4* A14 = (float4*)(sm + 8192);
    float4* A24 = (float4*)(sm + 12288);
    float*  Bm  = sm + 16384;
    float*  W2t = sm + 25088;
    float*  wsm = sm + 29696;
    float*  ysm = sm + 34048;
    float* redS = sm + 34304;
    float* redQ = sm + 34816;
    const uint32_t BmU = smem_u32(Bm), W2U = smem_u32(W2t);
    const int tid = threadIdx.x, wid = tid >> 5, lane = tid & 31;
    const int qr = lane >> 2, qc = lane & 3;
    const int e0 = blockIdx.x * 64;
    const int wm = wid & 1, wn = wid >> 1;
    const int n0 = wn * 16;
    const int Q = 8;

#define COMMIT_BMAIN(qq) do {                                                     \
    for (int s = tid; s < 2048; s += 512) {                                       \
        int k = s >> 5, n4 = s & 31;                                              \
        cpa16(BmU + (uint32_t)(k * 136 + n4 * 4) * 4,                             \
              g_wr + WVR_OFF + ((qq) * 64 + k) * 128 + n4 * 4);                   \
    }                                                                             \
    CPA_COMMIT(); } while (0)

    auto colbase = [](int qq) {
        return (qq < 4) ? 256 + qq * 64 : (qq < 6 ? 512 + (qq - 4) * 64
                                                  : 768 + (qq - 6) * 64);
    };

    // G1: W1 -> Bm
    for (int s = tid; s < 1024; s += 512) {
        int k = s >> 4, n4 = s & 15;
        cpa16(BmU + (uint32_t)(k * 72 + n4 * 4) * 4, g_wr + W1R_OFF + k * 64 + n4 * 4);
    }
    CPA_COMMIT();
    // G2: W2cols(0) = wB cols 256.. -> W2t
    for (int s = tid; s < 1024; s += 512) {
        int k = s >> 4, n4 = s & 15;
        cpa16(W2U + (uint32_t)(k * 72 + n4 * 4) * 4, g_wr + W2R_OFF + k * 896 + 256 + n4 * 4);
    }
    CPA_COMMIT();
    if (tid < 256) {
        int ge = e0 + (tid >> 2);
        ysm[tid] = (ge < E) ? eattr[(size_t)ge * 4 + (tid & 3)] : 0.f;
    }
    for (int qd = tid; qd < 1024; qd += 512) {
        int mt = qd >> 8, kg = (qd >> 5) & 7, ln = qd & 31;
        int ea = e0 + mt * 16 + (ln >> 2), ka = kg * 8 + (ln & 3);
        int eb = ea + 8;
        float v00 = (ea < E) ? es[(size_t)ea * 64 + ka] : 0.f;
        float v01 = (ea < E) ? es[(size_t)ea * 64 + ka + 4] : 0.f;
        float v10 = (eb < E) ? es[(size_t)eb * 64 + ka] : 0.f;
        float v11 = (eb < E) ? es[(size_t)eb * 64 + ka + 4] : 0.f;
        Ah4[qd] = make_float4(tf32r(v00), tf32r(v01), tf32r(v10), tf32r(v11));
    }
    CPA_WAIT1();
    __syncthreads();

    H_STAGE(sm, Ah4, Bm, redS, redQ)

    float accR[2][2][4];
    float accM[3][2][2][4];
#pragma unroll
    for (int mt = 0; mt < 2; mt++)
#pragma unroll
        for (int nt = 0; nt < 2; nt++)
#pragma unroll
            for (int f = 0; f < 4; f++) {
                accR[mt][nt][f] = 0.f;
#pragma unroll
                for (int m = 0; m < 3; m++) accM[m][mt][nt][f] = 0.f;
            }

    for (int q = 0; q < Q; q++) {
        CPA_WAIT1();
        __syncthreads();
        {
            int base = colbase(q);
            int nbn = (q + 1 < Q) ? colbase(q + 1) : -1;
            W_STAGE(Ah4, W2t, wsm, base, nbn)
        }
        // build A planes
        if (q < 4) {
            for (int qd = tid; qd < 1024; qd += 512) {
                int mt = qd >> 8, kg = (qd >> 5) & 7, ln = qd & 31;
                int ea = mt * 16 + (ln >> 2), ka = kg * 8 + (ln & 3);
                float v[4];
#pragma unroll
                for (int t = 0; t < 4; t++) {
                    int e = ea + (t >> 1) * 8, kk = ka + (t & 1) * 4;
                    int ge = e0 + e;
                    v[t] = (ge < E)
                         ? node[(size_t)ge * 640 + q * 64 + kk] * wsm[e * 68 + kk]
                         : 0.f;
                }
                A04[qd] = make_float4(tf32r(v[0]), tf32r(v[1]), tf32r(v[2]), tf32r(v[3]));
            }
        } else {
            for (int qd = tid; qd < 1024; qd += 512) {
                int mt = qd >> 8, kg = (qd >> 5) & 7, ln = qd & 31;
                int ea = mt * 16 + (ln >> 2), ka = kg * 8 + (ln & 3);
                float a0[4], a1[4], a2[4];
#pragma unroll
                for (int t = 0; t < 4; t++) {
                    int e = ea + (t >> 1) * 8, kk = ka + (t & 1) * 4;
                    int ge = e0 + e;
                    a0[t] = a1[t] = a2[t] = 0.f;
                    if (ge < E) {
                        if (q < 6) {
                            int j = (q - 4) * 64 + kk;
                            const float* xp = node + (size_t)ge * 640 + 256 + 3 * j;
                            float f = ysm[e * 4] * wsm[e * 68 + kk];
                            a0[t] = xp[0] * f; a1[t] = xp[1] * f; a2[t] = xp[2] * f;
                        } else {
                            int j = (q - 6) * 64 + kk;
                            const float* xp = node + (size_t)ge * 640 + 256 + 3 * j;
                            float x0v = xp[0], x1v = xp[1], x2v = xp[2];
                            float z0 = ysm[e * 4 + 1], z1 = ysm[e * 4 + 2], z2 = ysm[e * 4 + 3];
                            float f = S2 * wsm[e * 68 + kk];
                            a0[t] = (x1v * z2 - x2v * z1) * f;
                            a1[t] = (x2v * z0 - x0v * z2) * f;
                            a2[t] = (x0v * z1 - x1v * z0) * f;
                        }
                    }
                }
                A04[qd] = make_float4(tf32r(a0[0]), tf32r(a0[1]), tf32r(a0[2]), tf32r(a0[3]));
                A14[qd] = make_float4(tf32r(a1[0]), tf32r(a1[1]), tf32r(a1[2]), tf32r(a1[3]));
                A24[qd] = make_float4(tf32r(a2[0]), tf32r(a2[1]), tf32r(a2[2]), tf32r(a2[3]));
            }
        }
        if (q + 1 < Q) CPA_WAIT1(); else CPA_WAIT0();
        __syncthreads();
        if (q < 4) {
#pragma unroll
            for (int ks = 0; ks < 8; ks++) {
                uint32_t a0[4], a1[4];
                ldApk(a0, A04, wm * 2, ks, lane);
                ldApk(a1, A04, wm * 2 + 1, ks, lane);
#pragma unroll
                for (int nt = 0; nt < 2; nt++) {
                    uint32_t b[2];
                    ldBk(b, Bm, 136, n0 + nt * 8, ks * 8, qr, qc);
                    mma8(accR[0][nt], a0, b);
                    mma8(accR[1][nt], a1, b);
                }
            }
        } else {
#pragma unroll
            for (int ks = 0; ks < 8; ks++) {
                uint32_t b[2][2];
#pragma unroll
                for (int nt = 0; nt < 2; nt++) ldBk(b[nt], Bm, 136, n0 + nt * 8, ks * 8, qr, qc);
                const float4* Ap[3] = {A04, A14, A24};
#pragma unroll
                for (int m = 0; m < 3; m++) {
                    uint32_t a0[4], a1[4];
                    ldApk(a0, Ap[m], wm * 2, ks, lane);
                    ldApk(a1, Ap[m], wm * 2 + 1, ks, lane);
#pragma unroll
                    for (int nt = 0; nt < 2; nt++) {
                        mma8(accM[m][0][nt], a0, b[nt]);
                        mma8(accM[m][1][nt], a1, b[nt]);
                    }
                }
            }
        }
        __syncthreads();
        if (q + 1 < Q) COMMIT_BMAIN(q + 1);
    }

    // epilogue: fold R plane, sumsq, norm, write
#pragma unroll
    for (int mt = 0; mt < 2; mt++)
#pragma unroll
        for (int h = 0; h < 2; h++) {
            int e = wm * 32 + mt * 16 + qr + h * 8;
            float z0 = ysm[e * 4 + 1], z1 = ysm[e * 4 + 2], z2 = ysm[e * 4 + 3];
            float s = 0.f;
#pragma unroll
            for (int nt = 0; nt < 2; nt++)
#pragma unroll
                for (int c = 0; c < 2; c++) {
                    float R = accR[mt][nt][h * 2 + c];
                    float v0 = z0 * R + accM[0][mt][nt][h * 2 + c];
                    float v1 = z1 * R + accM[1][mt][nt][h * 2 + c];
                    float v2 = z2 * R + accM[2][mt][nt][h * 2 + c];
                    accM[0][mt][nt][h * 2 + c] = v0;
                    accM[1][mt][nt][h * 2 + c] = v1;
                    accM[2][mt][nt][h * 2 + c] = v2;
                    s += v0 * v0 + v1 * v1 + v2 * v2;
                }
            s = quad_sum(s);
            if (qc == 0) redQ[e * 8 + wn] = s;
        }
    __syncthreads();
    float cg[4];
#pragma unroll
    for (int nt = 0; nt < 2; nt++)
#pragma unroll
        for (int c = 0; c < 2; c++) cg[nt * 2 + c] = gv[n0 + nt * 8 + qc * 2 + c];
#pragma unroll
    for (int mt = 0; mt < 2; mt++)
#pragma unroll
        for (int h = 0; h < 2; h++) {
            int e = wm * 32 + mt * 16 + qr + h * 8, ge = e0 + e;
            float qt = 0.f;
#pragma unroll
            for (int w8 = 0; w8 < 8; w8++) qt += redQ[e * 8 + w8];
            float rstd = rsqrtf(qt * (1.f / 384.f) + EPS);
            if (ge < E) {
                float* ob = out + (size_t)ge * 640 + 256;
#pragma unroll
                for (int nt = 0; nt < 2; nt++)
#pragma unroll
                    for (int c = 0; c < 2; c++) {
                        int col = n0 + nt * 8 + qc * 2 + c;
                        float g = cg[nt * 2 + c] * rstd;
                        ob[3 * col + 0] = accM[0][mt][nt][h * 2 + c] * g;
                        ob[3 * col + 1] = accM[1][mt][nt][h * 2 + c] * g;
                        ob[3 * col + 2] = accM[2][mt][nt][h * 2 + c] * g;
                    }
            }
        }
#undef COMMIT_BMAIN
}

// ---------------------------------------------------------------------------
extern "C" void kernel_launch(void* const* d_in, const int* in_sizes, int n_in,
                              void* d_out, int out_size)
{
    const float* node  = (const float*)d_in[0];   // (E, 640)
    const float* eattr = (const float*)d_in[1];   // (E, 4)
    const float* escal = (const float*)d_in[2];   // (E, 64)
    const float* rW1   = (const float*)d_in[3];   // (64, 64)
    const float* rb1   = (const float*)d_in[4];   // (64,)
    const float* rlg   = (const float*)d_in[5];   // (64,)
    const float* rlb   = (const float*)d_in[6];   // (64,)
    const float* rW2   = (const float*)d_in[7];   // (64, 896)
    const float* roff  = (const float*)d_in[8];   // (896,)
    const float* Ws    = (const float*)d_in[9];   // (384, 256)
    const float* bs    = (const float*)d_in[10];  // (256,)
    const float* Wv    = (const float*)d_in[11];  // (512, 128)
    const float* gs    = (const float*)d_in[12];  // (256,)
    const float* gb    = (const float*)d_in[13];  // (256,)
    const float* gv    = (const float*)d_in[14];  // (128,)
    float* out = (float*)d_out;

    const int E = in_sizes[1] / 4;
    const int nb64 = (E + 63) / 64;

    cudaFuncSetAttribute(f2_s, cudaFuncAttributeMaxDynamicSharedMemorySize, F2_SMEM);
    cudaFuncSetAttribute(f3_v, cudaFuncAttributeMaxDynamicSharedMemorySize, F3_SMEM);

    k0_round<<<880, 256>>>(rW1, rW2, Ws, Wv);
    f2_s<<<nb64, 512, F2_SMEM>>>(node, eattr, escal, rb1, rlg, rlb, roff,
                                 bs, gs, gb, out, E);
    f3_v<<<nb64, 512, F3_SMEM>>>(node, eattr, escal, rb1, rlg, rlb, roff,
                                 gv, out, E);
}

// round 15
// speedup vs baseline: 1.2066x; 1.1159x over previous
#include <cuda_runtime.h>
#include <math.h>
#include <stdint.h>

#define S3 0.5773502691896258f
#define S2 0.7071067811865476f
#define EPS 1e-5f

// pre-rounded (tf32 rna) weights: W1[4096] | W2[57344] | Ws[98304] | Wv[65536]
__device__ float g_wr[225280];
#define W1R_OFF 0
#define W2R_OFF 4096
#define WSR_OFF 61440
#define WVR_OFF 159744

__device__ __forceinline__ float tf32r(float x) {
    uint32_t u;
    asm("cvt.rna.tf32.f32 %0, %1;" : "=r"(u) : "f"(x));
    return __uint_as_float(u);
}
// mma.sync m16n8k8 tf32: D += A(16x8) * B(8x8)^T, fp32 accum (baseline PTX, sm_80+)
__device__ __forceinline__ void mma8(float d[4], const uint32_t a[4], const uint32_t b[2]) {
    asm volatile(
        "mma.sync.aligned.m16n8k8.row.col.f32.tf32.tf32.f32 "
        "{%0,%1,%2,%3}, {%4,%5,%6,%7}, {%8,%9}, {%0,%1,%2,%3};"
        : "+f"(d[0]), "+f"(d[1]), "+f"(d[2]), "+f"(d[3])
        : "r"(a[0]), "r"(a[1]), "r"(a[2]), "r"(a[3]), "r"(b[0]), "r"(b[1]));
}
// Packed A tile: quad (mt,ks,lane) = [(r,k),(r,k+4),(r+8,k),(r+8,k+4)],
// r = mt*16 + lane/4, k = ks*8 + lane%4.  One LDS.128 per fragment.
__device__ __forceinline__ void ldApk(uint32_t a[4], const float4* Ap, int mt, int ks, int lane) {
    float4 v = Ap[(mt * 8 + ks) * 32 + lane];
    a[0] = __float_as_uint(v.x);
    a[1] = __float_as_uint(v.z);
    a[2] = __float_as_uint(v.y);
    a[3] = __float_as_uint(v.w);
}
// B fragment from row-major [k][n] tile, stride SB (SB % 32 == 8) -> conflict-free
__device__ __forceinline__ void ldBk(uint32_t b[2], const float* Bs, int SB,
                                     int n0, int k0, int qr, int qc) {
    b[0] = __float_as_uint(Bs[(k0 + qc) * SB + n0 + qr]);
    b[1] = __float_as_uint(Bs[(k0 + qc + 4) * SB + n0 + qr]);
}
__device__ __forceinline__ float quad_sum(float v) {
    v += __shfl_xor_sync(0xffffffffu, v, 1);
    v += __shfl_xor_sync(0xffffffffu, v, 2);
    return v;
}
__device__ __forceinline__ void cpa16(uint32_t saddr, const float* g) {
    asm volatile("cp.async.ca.shared.global [%0], [%1], 16;" :: "r"(saddr), "l"(g));
}
#define CPA_COMMIT() asm volatile("cp.async.commit_group;" ::: "memory")
#define CPA_WAIT0()  asm volatile("cp.async.wait_group 0;" ::: "memory")
#define CPA_WAIT1()  asm volatile("cp.async.wait_group 1;" ::: "memory")
__device__ __forceinline__ uint32_t smem_u32(const void* p) {
    return (uint32_t)__cvta_generic_to_shared(p);
}

// ---------------------------------------------------------------------------
// K0: pre-round weights to tf32 (rna) into g_wr.  225280 elems = 880x256.
// ---------------------------------------------------------------------------
__global__ __launch_bounds__(256) void k0_round(
    const float* __restrict__ W1, const float* __restrict__ W2,
    const float* __restrict__ Ws, const float* __restrict__ Wv)
{
    int i = blockIdx.x * 256 + threadIdx.x;
    float v;
    if (i < 4096)        v = W1[i];
    else if (i < 61440)  v = W2[i - 4096];
    else if (i < 159744) v = Ws[i - 61440];
    else                 v = Wv[i - 159744];
    g_wr[i] = tf32r(v);
}

// ===========================================================================
// FF: fully-fused kernel. 64 edges/block, 512 threads, 1 CTA/SM.
// Phase H: h = silu(LN(es@W1+b1)) (once).  Phase S: 6 chunks -> scalar out.
// Phase V: 8 chunks (4-plane) -> vector out.
// smem(floats), 141 KB total (L1D keeps 87 KB):
//   Ah 0..4095 (packed h, persists)
//   AsA0 4096..8191 (f2 As / f3 A0)
//   8192..25087: phase S -> Bm2 (Ws tile, SB=264)
//                phase V -> A1 8192 | A2 12288 | Bm3 16384..25087 (SB=136)
//   W2t 25088..29695 (SB=72) | wsm 29696..34047 (s68) | ysm 34048
//   redS 34304 | redQ 34816 | total 35328
// ===========================================================================
#define FF_SMEM (35328 * 4)
__global__ __launch_bounds__(512, 1) void ff(
    const float* __restrict__ node, const float* __restrict__ eattr,
    const float* __restrict__ es,
    const float* __restrict__ b1, const float* __restrict__ lg,
    const float* __restrict__ lb, const float* __restrict__ roff,
    const float* __restrict__ bs, const float* __restrict__ gs,
    const float* __restrict__ gb, const float* __restrict__ gv,
    float* __restrict__ out, int E)
{
    extern __shared__ float sm[];
    float4* Ah4 = (float4*)sm;
    float4* As4 = (float4*)(sm + 4096);          // phase S As / phase V A0
    float4* A14 = (float4*)(sm + 8192);          // phase V
    float4* A24 = (float4*)(sm + 12288);         // phase V
    float*  Bm2 = sm + 8192;                     // phase S (SB=264)
    float*  Bm3 = sm + 16384;                    // phase V (SB=136)
    float*  W2t = sm + 25088;
    float*  wsm = sm + 29696;
    float*  ysm = sm + 34048;
    float* redS = sm + 34304;
    float* redQ = sm + 34816;
    const uint32_t Bm2U = smem_u32(Bm2), Bm3U = smem_u32(Bm3), W2U = smem_u32(W2t);
    const int tid = threadIdx.x, wid = tid >> 5, lane = tid & 31;
    const int qr = lane >> 2, qc = lane & 3;
    const int e0 = blockIdx.x * 64;
    const int wm = wid & 1, wn = wid >> 1;

#define COMMIT_BM2(qq) do {                                                       \
    for (int s = tid; s < 4096; s += 512) {                                       \
        int k = s >> 6, n4 = s & 63;                                              \
        cpa16(Bm2U + (uint32_t)(k * 264 + n4 * 4) * 4,                            \
              g_wr + WSR_OFF + ((qq) * 64 + k) * 256 + n4 * 4);                   \
    }                                                                             \
    CPA_COMMIT(); } while (0)
#define COMMIT_BM3(qq) do {                                                       \
    for (int s = tid; s < 2048; s += 512) {                                       \
        int k = s >> 5, n4 = s & 31;                                              \
        cpa16(Bm3U + (uint32_t)(k * 136 + n4 * 4) * 4,                            \
              g_wr + WVR_OFF + ((qq) * 64 + k) * 128 + n4 * 4);                   \
    }                                                                             \
    CPA_COMMIT(); } while (0)

    auto colbase2 = [](int qq) { return (qq < 4) ? qq * 64 : 640 + (qq - 4) * 64; };
    auto colbase3 = [](int qq) {
        return (qq < 4) ? 256 + qq * 64 : (qq < 6 ? 512 + (qq - 4) * 64
                                                  : 768 + (qq - 6) * 64);
    };

    // w-slice MMA, merged-barrier (R14): wsm stores before the single sync,
    // W2(next) commit after it.
    auto w_stage = [&](int base, int nbn) {
        float wacc[2][4];
#pragma unroll
        for (int mt = 0; mt < 2; mt++)
#pragma unroll
            for (int f = 0; f < 4; f++) wacc[mt][f] = 0.f;
#pragma unroll
        for (int ks = 0; ks < 8; ks++) {
            uint32_t a0[4], a1[4], b[2];
            ldApk(a0, Ah4, wm * 2, ks, lane);
            ldApk(a1, Ah4, wm * 2 + 1, ks, lane);
            ldBk(b, W2t, 72, wn * 8, ks * 8, qr, qc);
            mma8(wacc[0], a0, b);
            mma8(wacc[1], a1, b);
        }
#pragma unroll
        for (int mt = 0; mt < 2; mt++)
#pragma unroll
            for (int h = 0; h < 2; h++) {
                int r = wm * 32 + mt * 16 + qr + h * 8;
#pragma unroll
                for (int c = 0; c < 2; c++) {
                    int u = wn * 8 + qc * 2 + c;
                    wsm[r * 68 + u] = wacc[mt][h * 2 + c] + roff[base + u];
                }
            }
        __syncthreads();                  // W2t reads done AND wsm visible
        if (nbn >= 0) {
            for (int s = tid; s < 1024; s += 512) {
                int k = s >> 4, n4 = s & 15;
                cpa16(W2U + (uint32_t)(k * 72 + n4 * 4) * 4,
                      g_wr + W2R_OFF + k * 896 + nbn + n4 * 4);
            }
            CPA_COMMIT();
        }
    };

    // -------- prologue: W1 -> Bm2 region (SB=72); W2c(S0) -> W2t; es; ysm ---
    for (int s = tid; s < 1024; s += 512) {
        int k = s >> 4, n4 = s & 15;
        cpa16(Bm2U + (uint32_t)(k * 72 + n4 * 4) * 4, g_wr + W1R_OFF + k * 64 + n4 * 4);
    }
    CPA_COMMIT();
    for (int s = tid; s < 1024; s += 512) {
        int k = s >> 4, n4 = s & 15;
        cpa16(W2U + (uint32_t)(k * 72 + n4 * 4) * 4, g_wr + W2R_OFF + k * 896 + n4 * 4);
    }
    CPA_COMMIT();
    if (tid < 256) {
        int ge = e0 + (tid >> 2);
        ysm[tid] = (ge < E) ? eattr[(size_t)ge * 4 + (tid & 3)] : 0.f;
    }
    for (int qd = tid; qd < 1024; qd += 512) {
        int mt = qd >> 8, kg = (qd >> 5) & 7, ln = qd & 31;
        int ea = e0 + mt * 16 + (ln >> 2), ka = kg * 8 + (ln & 3);
        int eb = ea + 8;
        float v00 = (ea < E) ? es[(size_t)ea * 64 + ka] : 0.f;
        float v01 = (ea < E) ? es[(size_t)ea * 64 + ka + 4] : 0.f;
        float v10 = (eb < E) ? es[(size_t)eb * 64 + ka] : 0.f;
        float v11 = (eb < E) ? es[(size_t)eb * 64 + ka + 4] : 0.f;
        Ah4[qd] = make_float4(tf32r(v00), tf32r(v01), tf32r(v10), tf32r(v11));
    }
    CPA_WAIT1();
    __syncthreads();

    // -------- H stage (once): h = silu(LN(es@W1 + b1)) -> Ah (packed) -------
    {
        float hacc[2][4];
#pragma unroll
        for (int mt = 0; mt < 2; mt++)
#pragma unroll
            for (int f = 0; f < 4; f++) hacc[mt][f] = 0.f;
#pragma unroll
        for (int ks = 0; ks < 8; ks++) {
            uint32_t a0[4], a1[4], b[2];
            ldApk(a0, Ah4, wm * 2, ks, lane);
            ldApk(a1, Ah4, wm * 2 + 1, ks, lane);
            ldBk(b, Bm2, 72, wn * 8, ks * 8, qr, qc);
            mma8(hacc[0], a0, b);
            mma8(hacc[1], a1, b);
        }
        __syncthreads();      // done reading W1 (Bm2 region) and es (Ah)
        COMMIT_BM2(0);        // Ws chunk 0 overwrites W1 region
        float cb[2], cgl[2], cBl[2];
#pragma unroll
        for (int c = 0; c < 2; c++) {
            int col = wn * 8 + qc * 2 + c;
            cb[c] = b1[col]; cgl[c] = lg[col]; cBl[c] = lb[col];
        }
#pragma unroll
        for (int mt = 0; mt < 2; mt++)
#pragma unroll
            for (int h = 0; h < 2; h++) {
                float s = 0.f, q2 = 0.f;
#pragma unroll
                for (int c = 0; c < 2; c++) {
                    float v = hacc[mt][h * 2 + c] + cb[c];
                    hacc[mt][h * 2 + c] = v;
                    s += v; q2 += v * v;
                }
                s = quad_sum(s); q2 = quad_sum(q2);
                if (qc == 0) {
                    int r = wm * 32 + mt * 16 + qr + h * 8;
                    redS[r * 8 + wn] = s; redQ[r * 8 + wn] = q2;
                }
            }
        __syncthreads();
#pragma unroll
        for (int mt = 0; mt < 2; mt++)
#pragma unroll
            for (int h = 0; h < 2; h++) {
                int r = wm * 32 + mt * 16 + qr + h * 8;
                float s = 0.f, q2 = 0.f;
#pragma unroll
                for (int w8 = 0; w8 < 8; w8++) {
                    s += redS[r * 8 + w8]; q2 += redQ[r * 8 + w8];
                }
                float mu = s * (1.f / 64.f);
                float rstd = rsqrtf(fmaxf(q2 * (1.f / 64.f) - mu * mu, 0.f) + EPS);
                int mtp = wm * 2 + mt;
#pragma unroll
                for (int c = 0; c < 2; c++) {
                    float v = (hacc[mt][h * 2 + c] - mu) * rstd * cgl[c] + cBl[c];
                    v = v / (1.f + expf(-v));
                    int col = wn * 8 + qc * 2 + c;
                    int word = ((mtp * 8 + (col >> 3)) * 32 + qr * 4 + (col & 3)) * 4
                               + h * 2 + ((col >> 2) & 1);
                    sm[word] = tf32r(v);
                }
            }
        __syncthreads();
    }

    // ======================= Phase S: scalar path ==========================
    {
        float acc[2][4][4];
#pragma unroll
        for (int mt = 0; mt < 2; mt++)
#pragma unroll
            for (int nt = 0; nt < 4; nt++)
#pragma unroll
                for (int f = 0; f < 4; f++) acc[mt][nt][f] = 0.f;

        for (int q = 0; q < 6; q++) {
            CPA_WAIT1();              // W2t(q) ready (Bm2(q) may pend)
            __syncthreads();
            // next W2 slice: S chunks 1..5, then V chunk 0 (cols 256)
            int nbn = (q < 5) ? colbase2(q + 1) : colbase3(0);
            w_stage(colbase2(q), nbn);
            // build As(q)
            for (int qd = tid; qd < 1024; qd += 512) {
                int mt = qd >> 8, kg = (qd >> 5) & 7, ln = qd & 31;
                int ea = mt * 16 + (ln >> 2), ka = kg * 8 + (ln & 3);
                float v[4];
#pragma unroll
                for (int t = 0; t < 4; t++) {
                    int e = ea + (t >> 1) * 8, kk = ka + (t & 1) * 4;
                    int ge = e0 + e;
                    v[t] = 0.f;
                    if (ge < E) {
                        if (q < 4) {
                            v[t] = node[(size_t)ge * 640 + q * 64 + kk] * ysm[e * 4]
                                 * wsm[e * 68 + kk];
                        } else {
                            int j = (q - 4) * 64 + kk;
                            const float* xp = node + (size_t)ge * 640 + 256 + 3 * j;
                            float d = xp[0] * ysm[e * 4 + 1] + xp[1] * ysm[e * 4 + 2]
                                    + xp[2] * ysm[e * 4 + 3];
                            v[t] = S3 * d * wsm[e * 68 + kk];
                        }
                    }
                }
                As4[qd] = make_float4(tf32r(v[0]), tf32r(v[1]), tf32r(v[2]), tf32r(v[3]));
            }
            CPA_WAIT1();              // Bm2(q) ready (W2t(next) pends)
            __syncthreads();
#pragma unroll
            for (int ks = 0; ks < 8; ks++) {
                uint32_t a0[4], a1[4];
                ldApk(a0, As4, wm * 2, ks, lane);
                ldApk(a1, As4, wm * 2 + 1, ks, lane);
#pragma unroll
                for (int nt = 0; nt < 4; nt++) {
                    uint32_t b[2];
                    ldBk(b, Bm2, 264, wn * 32 + nt * 8, ks * 8, qr, qc);
                    mma8(acc[0][nt], a0, b);
                    mma8(acc[1][nt], a1, b);
                }
            }
            __syncthreads();
            if (q < 5) COMMIT_BM2(q + 1);
            else       COMMIT_BM3(0);   // first Wv tile flies during epilogue
        }

        // ---- phase-S epilogue: +bias, LN over 256 cols, write ----
        float cbv[8], cgv[8], cBv[8];
#pragma unroll
        for (int nt = 0; nt < 4; nt++)
#pragma unroll
            for (int c = 0; c < 2; c++) {
                int col = wn * 32 + nt * 8 + qc * 2 + c;
                cbv[nt * 2 + c] = bs[col]; cgv[nt * 2 + c] = gs[col]; cBv[nt * 2 + c] = gb[col];
            }
#pragma unroll
        for (int mt = 0; mt < 2; mt++)
#pragma unroll
            for (int h = 0; h < 2; h++) {
                float s = 0.f, q2 = 0.f;
#pragma unroll
                for (int nt = 0; nt < 4; nt++)
#pragma unroll
                    for (int c = 0; c < 2; c++) {
                        float v = acc[mt][nt][h * 2 + c] + cbv[nt * 2 + c];
                        acc[mt][nt][h * 2 + c] = v;
                        s += v; q2 += v * v;
                    }
                s = quad_sum(s); q2 = quad_sum(q2);
                if (qc == 0) {
                    int r = wm * 32 + mt * 16 + qr + h * 8;
                    redS[r * 8 + wn] = s; redQ[r * 8 + wn] = q2;
                }
            }
        __syncthreads();
#pragma unroll
        for (int mt = 0; mt < 2; mt++)
#pragma unroll
            for (int h = 0; h < 2; h++) {
                int r = wm * 32 + mt * 16 + qr + h * 8, ge = e0 + r;
                float s = 0.f, q2 = 0.f;
#pragma unroll
                for (int w8 = 0; w8 < 8; w8++) { s += redS[r * 8 + w8]; q2 += redQ[r * 8 + w8]; }
                float mu = s * (1.f / 256.f);
                float rstd = rsqrtf(fmaxf(q2 * (1.f / 256.f) - mu * mu, 0.f) + EPS);
                if (ge < E) {
#pragma unroll
                    for (int nt = 0; nt < 4; nt++) {
                        int col = wn * 32 + nt * 8 + qc * 2;
                        float2 v;
                        v.x = (acc[mt][nt][h * 2] - mu) * rstd * cgv[nt * 2] + cBv[nt * 2];
                        v.y = (acc[mt][nt][h * 2 + 1] - mu) * rstd * cgv[nt * 2 + 1] + cBv[nt * 2 + 1];
                        *(float2*)&out[(size_t)ge * 640 + col] = v;
                    }
                }
            }
    }

    // ======================= Phase V: vector path ==========================
    {
        const int n0 = wn * 16;
        float accR[2][2][4];
        float accM[3][2][2][4];
#pragma unroll
        for (int mt = 0; mt < 2; mt++)
#pragma unroll
            for (int nt = 0; nt < 2; nt++)
#pragma unroll
                for (int f = 0; f < 4; f++) {
                    accR[mt][nt][f] = 0.f;
#pragma unroll
                    for (int m = 0; m < 3; m++) accM[m][mt][nt][f] = 0.f;
                }

        for (int q = 0; q < 8; q++) {
            CPA_WAIT1();              // W2t(Vq) ready (Bm3(q) may pend)
            __syncthreads();
            int nbn = (q < 7) ? colbase3(q + 1) : -1;
            w_stage(colbase3(q), nbn);
            // build A planes
            if (q < 4) {
                for (int qd = tid; qd < 1024; qd += 512) {
                    int mt = qd >> 8, kg = (qd >> 5) & 7, ln = qd & 31;
                    int ea = mt * 16 + (ln >> 2), ka = kg * 8 + (ln & 3);
                    float v[4];
#pragma unroll
                    for (int t = 0; t < 4; t++) {
                        int e = ea + (t >> 1) * 8, kk = ka + (t & 1) * 4;
                        int ge = e0 + e;
                        v[t] = (ge < E)
                             ? node[(size_t)ge * 640 + q * 64 + kk] * wsm[e * 68 + kk]
                             : 0.f;
                    }
                    As4[qd] = make_float4(tf32r(v[0]), tf32r(v[1]), tf32r(v[2]), tf32r(v[3]));
                }
            } else {
                for (int qd = tid; qd < 1024; qd += 512) {
                    int mt = qd >> 8, kg = (qd >> 5) & 7, ln = qd & 31;
                    int ea = mt * 16 + (ln >> 2), ka = kg * 8 + (ln & 3);
                    float a0[4], a1[4], a2[4];
#pragma unroll
                    for (int t = 0; t < 4; t++) {
                        int e = ea + (t >> 1) * 8, kk = ka + (t & 1) * 4;
                        int ge = e0 + e;
                        a0[t] = a1[t] = a2[t] = 0.f;
                        if (ge < E) {
                            if (q < 6) {
                                int j = (q - 4) * 64 + kk;
                                const float* xp = node + (size_t)ge * 640 + 256 + 3 * j;
                                float f = ysm[e * 4] * wsm[e * 68 + kk];
                                a0[t] = xp[0] * f; a1[t] = xp[1] * f; a2[t] = xp[2] * f;
                            } else {
                                int j = (q - 6) * 64 + kk;
                                const float* xp = node + (size_t)ge * 640 + 256 + 3 * j;
                                float x0v = xp[0], x1v = xp[1], x2v = xp[2];
                                float z0 = ysm[e * 4 + 1], z1 = ysm[e * 4 + 2], z2 = ysm[e * 4 + 3];
                                float f = S2 * wsm[e * 68 + kk];
                                a0[t] = (x1v * z2 - x2v * z1) * f;
                                a1[t] = (x2v * z0 - x0v * z2) * f;
                                a2[t] = (x0v * z1 - x1v * z0) * f;
                            }
                        }
                    }
                    As4[qd] = make_float4(tf32r(a0[0]), tf32r(a0[1]), tf32r(a0[2]), tf32r(a0[3]));
                    A14[qd] = make_float4(tf32r(a1[0]), tf32r(a1[1]), tf32r(a1[2]), tf32r(a1[3]));
                    A24[qd] = make_float4(tf32r(a2[0]), tf32r(a2[1]), tf32r(a2[2]), tf32r(a2[3]));
                }
            }
            if (q < 7) CPA_WAIT1(); else CPA_WAIT0();   // Bm3(q) ready
            __syncthreads();
            if (q < 4) {
#pragma unroll
                for (int ks = 0; ks < 8; ks++) {
                    uint32_t a0[4], a1[4];
                    ldApk(a0, As4, wm * 2, ks, lane);
                    ldApk(a1, As4, wm * 2 + 1, ks, lane);
#pragma unroll
                    for (int nt = 0; nt < 2; nt++) {
                        uint32_t b[2];
                        ldBk(b, Bm3, 136, n0 + nt * 8, ks * 8, qr, qc);
                        mma8(accR[0][nt], a0, b);
                        mma8(accR[1][nt], a1, b);
                    }
                }
            } else {
#pragma unroll
                for (int ks = 0; ks < 8; ks++) {
                    uint32_t b[2][2];
#pragma unroll
                    for (int nt = 0; nt < 2; nt++) ldBk(b[nt], Bm3, 136, n0 + nt * 8, ks * 8, qr, qc);
                    const float4* Ap[3] = {As4, A14, A24};
#pragma unroll
                    for (int m = 0; m < 3; m++) {
                        uint32_t a0[4], a1[4];
                        ldApk(a0, Ap[m], wm * 2, ks, lane);
                        ldApk(a1, Ap[m], wm * 2 + 1, ks, lane);
#pragma unroll
                        for (int nt = 0; nt < 2; nt++) {
                            mma8(accM[m][0][nt], a0, b[nt]);
                            mma8(accM[m][1][nt], a1, b[nt]);
                        }
                    }
                }
            }
            __syncthreads();
            if (q < 7) COMMIT_BM3(q + 1);
        }

        // ---- phase-V epilogue: fold R plane, sumsq, norm, write ----
#pragma unroll
        for (int mt = 0; mt < 2; mt++)
#pragma unroll
            for (int h = 0; h < 2; h++) {
                int e = wm * 32 + mt * 16 + qr + h * 8;
                float z0 = ysm[e * 4 + 1], z1 = ysm[e * 4 + 2], z2 = ysm[e * 4 + 3];
                float s = 0.f;
#pragma unroll
                for (int nt = 0; nt < 2; nt++)
#pragma unroll
                    for (int c = 0; c < 2; c++) {
                        float R = accR[mt][nt][h * 2 + c];
                        float v0 = z0 * R + accM[0][mt][nt][h * 2 + c];
                        float v1 = z1 * R + accM[1][mt][nt][h * 2 + c];
                        float v2 = z2 * R + accM[2][mt][nt][h * 2 + c];
                        accM[0][mt][nt][h * 2 + c] = v0;
                        accM[1][mt][nt][h * 2 + c] = v1;
                        accM[2][mt][nt][h * 2 + c] = v2;
                        s += v0 * v0 + v1 * v1 + v2 * v2;
                    }
                s = quad_sum(s);
                if (qc == 0) redQ[e * 8 + wn] = s;
            }
        __syncthreads();
        float cg[4];
#pragma unroll
        for (int nt = 0; nt < 2; nt++)
#pragma unroll
            for (int c = 0; c < 2; c++) cg[nt * 2 + c] = gv[n0 + nt * 8 + qc * 2 + c];
#pragma unroll
        for (int mt = 0; mt < 2; mt++)
#pragma unroll
            for (int h = 0; h < 2; h++) {
                int e = wm * 32 + mt * 16 + qr + h * 8, ge = e0 + e;
                float qt = 0.f;
#pragma unroll
                for (int w8 = 0; w8 < 8; w8++) qt += redQ[e * 8 + w8];
                float rstd = rsqrtf(qt * (1.f / 384.f) + EPS);
                if (ge < E) {
                    float* ob = out + (size_t)ge * 640 + 256;
#pragma unroll
                    for (int nt = 0; nt < 2; nt++)
#pragma unroll
                        for (int c = 0; c < 2; c++) {
                            int col = n0 + nt * 8 + qc * 2 + c;
                            float g = cg[nt * 2 + c] * rstd;
                            ob[3 * col + 0] = accM[0][mt][nt][h * 2 + c] * g;
                            ob[3 * col + 1] = accM[1][mt][nt][h * 2 + c] * g;
                            ob[3 * col + 2] = accM[2][mt][nt][h * 2 + c] * g;
                        }
                }
            }
    }
#undef COMMIT_BM2
#undef COMMIT_BM3
}

// ---------------------------------------------------------------------------
extern "C" void kernel_launch(void* const* d_in, const int* in_sizes, int n_in,
                              void* d_out, int out_size)
{
    const float* node  = (const float*)d_in[0];   // (E, 640)
    const float* eattr = (const float*)d_in[1];   // (E, 4)
    const float* escal = (const float*)d_in[2];   // (E, 64)
    const float* rW1   = (const float*)d_in[3];   // (64, 64)
    const float* rb1   = (const float*)d_in[4];   // (64,)
    const float* rlg   = (const float*)d_in[5];   // (64,)
    const float* rlb   = (const float*)d_in[6];   // (64,)
    const float* rW2   = (const float*)d_in[7];   // (64, 896)
    const float* roff  = (const float*)d_in[8];   // (896,)
    const float* Ws    = (const float*)d_in[9];   // (384, 256)
    const float* bs    = (const float*)d_in[10];  // (256,)
    const float* Wv    = (const float*)d_in[11];  // (512, 128)
    const float* gs    = (const float*)d_in[12];  // (256,)
    const float* gb    = (const float*)d_in[13];  // (256,)
    const float* gv    = (const float*)d_in[14];  // (128,)
    float* out = (float*)d_out;

    const int E = in_sizes[1] / 4;
    const int nb64 = (E + 63) / 64;

    cudaFuncSetAttribute(ff, cudaFuncAttributeMaxDynamicSharedMemorySize, FF_SMEM);

    k0_round<<<880, 256>>>(rW1, rW2, Ws, Wv);
    ff<<<nb64, 512, FF_SMEM>>>(node, eattr, escal, rb1, rlg, rlb, roff,
                               bs, gs, gb, gv, out, E);
}

// round 17
// speedup vs baseline: 1.2248x; 1.0151x over previous
#include <cuda_runtime.h>
#include <math.h>
#include <stdint.h>

#define S3 0.5773502691896258f
#define S2 0.7071067811865476f
#define EPS 1e-5f

// Pre-packed tf32(rna) weights in MMA-quad layout.
// float2 quad (ng,ks,lane) = [B(n,k), B(n,k+4)], n = ng*8 + lane/4,
// k = ks*8 + lane%4.  One conflict-free LDS.64 per B fragment.
// float2 units: W1P 0 (2048) | W2P 2048 (14 slices x 2048)
//             | WSP 30720 (6 chunks x 8192) | WVP 79872 (8 chunks x 4096)
__device__ float g_wp[225280];   // 112640 float2
#define W1P 0
#define W2P 2048
#define WSP 30720
#define WVP 79872

__device__ __forceinline__ float tf32r(float x) {
    uint32_t u;
    asm("cvt.rna.tf32.f32 %0, %1;" : "=r"(u) : "f"(x));
    return __uint_as_float(u);
}
// mma.sync m16n8k8 tf32: D += A(16x8) * B(8x8)^T, fp32 accum (baseline PTX, sm_80+)
__device__ __forceinline__ void mma8(float d[4], const uint32_t a[4], const uint32_t b[2]) {
    asm volatile(
        "mma.sync.aligned.m16n8k8.row.col.f32.tf32.tf32.f32 "
        "{%0,%1,%2,%3}, {%4,%5,%6,%7}, {%8,%9}, {%0,%1,%2,%3};"
        : "+f"(d[0]), "+f"(d[1]), "+f"(d[2]), "+f"(d[3])
        : "r"(a[0]), "r"(a[1]), "r"(a[2]), "r"(a[3]), "r"(b[0]), "r"(b[1]));
}
// Packed A tile: quad (mt,ks,lane) = [(r,k),(r,k+4),(r+8,k),(r+8,k+4)]
__device__ __forceinline__ void ldApk(uint32_t a[4], const float4* Ap, int mt, int ks, int lane) {
    float4 v = Ap[(mt * 8 + ks) * 32 + lane];
    a[0] = __float_as_uint(v.x);
    a[1] = __float_as_uint(v.z);
    a[2] = __float_as_uint(v.y);
    a[3] = __float_as_uint(v.w);
}
// Packed B fragment: one LDS.64
__device__ __forceinline__ void ldBpk(uint32_t b[2], const float* Bp, int ng, int ks, int lane) {
    float2 v = ((const float2*)Bp)[(ng * 8 + ks) * 32 + lane];
    b[0] = __float_as_uint(v.x);
    b[1] = __float_as_uint(v.y);
}
__device__ __forceinline__ float quad_sum(float v) {
    v += __shfl_xor_sync(0xffffffffu, v, 1);
    v += __shfl_xor_sync(0xffffffffu, v, 2);
    return v;
}
__device__ __forceinline__ void cpa16(uint32_t saddr, const float* g) {
    asm volatile("cp.async.ca.shared.global [%0], [%1], 16;" :: "r"(saddr), "l"(g));
}
#define CPA_COMMIT() asm volatile("cp.async.commit_group;" ::: "memory")
#define CPA_WAIT0()  asm volatile("cp.async.wait_group 0;" ::: "memory")
#define CPA_WAIT1()  asm volatile("cp.async.wait_group 1;" ::: "memory")
__device__ __forceinline__ uint32_t smem_u32(const void* p) {
    return (uint32_t)__cvta_generic_to_shared(p);
}

// ---------------------------------------------------------------------------
// K0: round weights to tf32 AND pack into quad layout.  112640 float2 elems.
// ---------------------------------------------------------------------------
__global__ __launch_bounds__(256) void k0_pack(
    const float* __restrict__ W1, const float* __restrict__ W2,
    const float* __restrict__ Ws, const float* __restrict__ Wv)
{
    int i = blockIdx.x * 256 + threadIdx.x;   // float2 index
    float a, b;
    if (i < 2048) {                 // W1 (64n x 64k): 2048 quads
        int ng = i >> 8, ks = (i >> 5) & 7, ln = i & 31;
        int n = ng * 8 + (ln >> 2), k = ks * 8 + (ln & 3);
        a = W1[k * 64 + n]; b = W1[(k + 4) * 64 + n];
    } else if (i < 30720) {         // W2: 14 slices of 64n x 64k (2048 quads each)
        int j = i - 2048;
        int s = j >> 11, r = j & 2047;
        int ng = r >> 8, ks = (r >> 5) & 7, ln = r & 31;
        int n = s * 64 + ng * 8 + (ln >> 2), k = ks * 8 + (ln & 3);
        a = W2[(size_t)k * 896 + n]; b = W2[(size_t)(k + 4) * 896 + n];
    } else if (i < 79872) {         // Ws: 6 chunks of 256n x 64k (8192 quads)
        int j = i - 30720;
        int q = j >> 13, r = j & 8191;
        int ng = r >> 8, ks = (r >> 5) & 7, ln = r & 31;
        int n = ng * 8 + (ln >> 2), k = q * 64 + ks * 8 + (ln & 3);
        a = Ws[(size_t)k * 256 + n]; b = Ws[(size_t)(k + 4) * 256 + n];
    } else {                        // Wv: 8 chunks of 128n x 64k (4096 quads)
        int j = i - 79872;
        int q = j >> 12, r = j & 4095;
        int ng = r >> 8, ks = (r >> 5) & 7, ln = r & 31;
        int n = ng * 8 + (ln >> 2), k = q * 64 + ks * 8 + (ln & 3);
        a = Wv[(size_t)k * 128 + n]; b = Wv[(size_t)(k + 4) * 128 + n];
    }
    g_wp[2 * i]     = tf32r(a);
    g_wp[2 * i + 1] = tf32r(b);
}

// ===========================================================================
// FF: fully-fused kernel. 64 edges/block, 512 threads, 1 CTA/SM.
// smem(floats), 141 KB (L1D keeps 87 KB):
//   Ah 0..4095 (packed h) | AsA0 4096..8191
//   8192..: phase S -> Bp2 (packed Ws chunk, 16384 floats, 8192..24575)
//           phase V -> A1 8192 | A2 12288 | Bp3 16384..24575 (packed Wv, 8192)
//   W2p 25088..29183 (packed 64-col slice, 4096 floats) | wsm 29696..34047 (s68)
//   ysm 34048 | redS 34304 | redQ 34816 | total 35328
// ===========================================================================
#define FF_SMEM (35328 * 4)
__global__ __launch_bounds__(512, 1) void ff(
    const float* __restrict__ node, const float* __restrict__ eattr,
    const float* __restrict__ es,
    const float* __restrict__ b1, const float* __restrict__ lg,
    const float* __restrict__ lb, const float* __restrict__ roff,
    const float* __restrict__ bs, const float* __restrict__ gs,
    const float* __restrict__ gb, const float* __restrict__ gv,
    float* __restrict__ out, int E)
{
    extern __shared__ float sm[];
    float4* Ah4 = (float4*)sm;
    float4* As4 = (float4*)(sm + 4096);          // phase S As / phase V A0
    float4* A14 = (float4*)(sm + 8192);          // phase V
    float4* A24 = (float4*)(sm + 12288);         // phase V
    float*  Bp2 = sm + 8192;                     // phase S packed Ws (+ W1 at start)
    float*  Bp3 = sm + 16384;                    // phase V packed Wv
    float*  W2p = sm + 25088;                    // packed W2 slice (4096 floats)
    float*  wsm = sm + 29696;
    float*  ysm = sm + 34048;
    float* redS = sm + 34304;
    float* redQ = sm + 34816;
    const uint32_t Bp2U = smem_u32(Bp2), Bp3U = smem_u32(Bp3), W2U = smem_u32(W2p);
    const int tid = threadIdx.x, wid = tid >> 5, lane = tid & 31;
    const int qr = lane >> 2, qc = lane & 3;
    const int e0 = blockIdx.x * 64;
    const int wm = wid & 1, wn = wid >> 1;

#define COMMIT_BM2(qq) do {                                                       \
    for (int s = tid; s < 4096; s += 512)                                         \
        cpa16(Bp2U + (uint32_t)s * 16, g_wp + (WSP + (qq) * 8192) * 2 + s * 4);   \
    CPA_COMMIT(); } while (0)
#define COMMIT_BM3(qq) do {                                                       \
    for (int s = tid; s < 2048; s += 512)                                         \
        cpa16(Bp3U + (uint32_t)s * 16, g_wp + (WVP + (qq) * 4096) * 2 + s * 4);   \
    CPA_COMMIT(); } while (0)

    auto colbase2 = [](int qq) { return (qq < 4) ? qq * 64 : 640 + (qq - 4) * 64; };
    auto colbase3 = [](int qq) {
        return (qq < 4) ? 256 + qq * 64 : (qq < 6 ? 512 + (qq - 4) * 64
                                                  : 768 + (qq - 6) * 64);
    };

    // w-slice MMA, merged-barrier: wsm stores before the single sync,
    // W2(next slice) commit after it.  base = roff column base; nsl = next slice.
    auto w_stage = [&](int base, int nsl) {
        float wacc[2][4];
#pragma unroll
        for (int mt = 0; mt < 2; mt++)
#pragma unroll
            for (int f = 0; f < 4; f++) wacc[mt][f] = 0.f;
#pragma unroll
        for (int ks = 0; ks < 8; ks++) {
            uint32_t a0[4], a1[4], b[2];
            ldApk(a0, Ah4, wm * 2, ks, lane);
            ldApk(a1, Ah4, wm * 2 + 1, ks, lane);
            ldBpk(b, W2p, wn, ks, lane);
            mma8(wacc[0], a0, b);
            mma8(wacc[1], a1, b);
        }
#pragma unroll
        for (int mt = 0; mt < 2; mt++)
#pragma unroll
            for (int h = 0; h < 2; h++) {
                int r = wm * 32 + mt * 16 + qr + h * 8;
#pragma unroll
                for (int c = 0; c < 2; c++) {
                    int u = wn * 8 + qc * 2 + c;
                    wsm[r * 68 + u] = wacc[mt][h * 2 + c] + roff[base + u];
                }
            }
        __syncthreads();                  // W2p reads done AND wsm visible
        if (nsl >= 0) {
            for (int s = tid; s < 1024; s += 512)
                cpa16(W2U + (uint32_t)s * 16, g_wp + (W2P + nsl * 2048) * 2 + s * 4);
            CPA_COMMIT();
        }
    };

    // -------- prologue: W1(packed) -> Bp2; W2 slice 0 -> W2p; es; ysm -------
    for (int s = tid; s < 1024; s += 512)
        cpa16(Bp2U + (uint32_t)s * 16, g_wp + W1P * 2 + s * 4);
    CPA_COMMIT();
    for (int s = tid; s < 1024; s += 512)
        cpa16(W2U + (uint32_t)s * 16, g_wp + W2P * 2 + s * 4);
    CPA_COMMIT();
    if (tid < 256) {
        int ge = e0 + (tid >> 2);
        ysm[tid] = (ge < E) ? eattr[(size_t)ge * 4 + (tid & 3)] : 0.f;
    }
    for (int qd = tid; qd < 1024; qd += 512) {
        int mt = qd >> 8, kg = (qd >> 5) & 7, ln = qd & 31;
        int ea = e0 + mt * 16 + (ln >> 2), ka = kg * 8 + (ln & 3);
        int eb = ea + 8;
        float v00 = (ea < E) ? es[(size_t)ea * 64 + ka] : 0.f;
        float v01 = (ea < E) ? es[(size_t)ea * 64 + ka + 4] : 0.f;
        float v10 = (eb < E) ? es[(size_t)eb * 64 + ka] : 0.f;
        float v11 = (eb < E) ? es[(size_t)eb * 64 + ka + 4] : 0.f;
        Ah4[qd] = make_float4(tf32r(v00), tf32r(v01), tf32r(v10), tf32r(v11));
    }
    CPA_WAIT1();
    __syncthreads();

    // -------- H stage (once): h = silu(LN(es@W1 + b1)) -> Ah (packed) -------
    {
        float hacc[2][4];
#pragma unroll
        for (int mt = 0; mt < 2; mt++)
#pragma unroll
            for (int f = 0; f < 4; f++) hacc[mt][f] = 0.f;
#pragma unroll
        for (int ks = 0; ks < 8; ks++) {
            uint32_t a0[4], a1[4], b[2];
            ldApk(a0, Ah4, wm * 2, ks, lane);
            ldApk(a1, Ah4, wm * 2 + 1, ks, lane);
            ldBpk(b, Bp2, wn, ks, lane);
            mma8(hacc[0], a0, b);
            mma8(hacc[1], a1, b);
        }
        __syncthreads();      // done reading W1 (Bp2 region) and es (Ah)
        COMMIT_BM2(0);        // packed Ws chunk 0 overwrites W1 region
        float cb[2], cgl[2], cBl[2];
#pragma unroll
        for (int c = 0; c < 2; c++) {
            int col = wn * 8 + qc * 2 + c;
            cb[c] = b1[col]; cgl[c] = lg[col]; cBl[c] = lb[col];
        }
#pragma unroll
        for (int mt = 0; mt < 2; mt++)
#pragma unroll
            for (int h = 0; h < 2; h++) {
                float s = 0.f, q2 = 0.f;
#pragma unroll
                for (int c = 0; c < 2; c++) {
                    float v = hacc[mt][h * 2 + c] + cb[c];
                    hacc[mt][h * 2 + c] = v;
                    s += v; q2 += v * v;
                }
                s = quad_sum(s); q2 = quad_sum(q2);
                if (qc == 0) {
                    int r = wm * 32 + mt * 16 + qr + h * 8;
                    redS[r * 8 + wn] = s; redQ[r * 8 + wn] = q2;
                }
            }
        __syncthreads();
#pragma unroll
        for (int mt = 0; mt < 2; mt++)
#pragma unroll
            for (int h = 0; h < 2; h++) {
                int r = wm * 32 + mt * 16 + qr + h * 8;
                float s = 0.f, q2 = 0.f;
#pragma unroll
                for (int w8 = 0; w8 < 8; w8++) {
                    s += redS[r * 8 + w8]; q2 += redQ[r * 8 + w8];
                }
                float mu = s * (1.f / 64.f);
                float rstd = rsqrtf(fmaxf(q2 * (1.f / 64.f) - mu * mu, 0.f) + EPS);
                int mtp = wm * 2 + mt;
#pragma unroll
                for (int c = 0; c < 2; c++) {
                    float v = (hacc[mt][h * 2 + c] - mu) * rstd * cgl[c] + cBl[c];
                    v = v / (1.f + expf(-v));
                    int col = wn * 8 + qc * 2 + c;
                    int word = ((mtp * 8 + (col >> 3)) * 32 + qr * 4 + (col & 3)) * 4
                               + h * 2 + ((col >> 2) & 1);
                    sm[word] = tf32r(v);
                }
            }
        __syncthreads();
    }

    // ======================= Phase S: scalar path ==========================
    {
        float acc[2][4][4];
#pragma unroll
        for (int mt = 0; mt < 2; mt++)
#pragma unroll
            for (int nt = 0; nt < 4; nt++)
#pragma unroll
                for (int f = 0; f < 4; f++) acc[mt][nt][f] = 0.f;

        for (int q = 0; q < 6; q++) {
            CPA_WAIT1();              // W2p(q) ready (Bp2(q) may pend)
            __syncthreads();
            int base = colbase2(q);
            int nsl = (q < 5) ? (colbase2(q + 1) >> 6) : (colbase3(0) >> 6);
            w_stage(base, nsl);
            // build As(q)
            for (int qd = tid; qd < 1024; qd += 512) {
                int mt = qd >> 8, kg = (qd >> 5) & 7, ln = qd & 31;
                int ea = mt * 16 + (ln >> 2), ka = kg * 8 + (ln & 3);
                float v[4];
#pragma unroll
                for (int t = 0; t < 4; t++) {
                    int e = ea + (t >> 1) * 8, kk = ka + (t & 1) * 4;
                    int ge = e0 + e;
                    v[t] = 0.f;
                    if (ge < E) {
                        if (q < 4) {
                            v[t] = node[(size_t)ge * 640 + q * 64 + kk] * ysm[e * 4]
                                 * wsm[e * 68 + kk];
                        } else {
                            int j = (q - 4) * 64 + kk;
                            const float* xp = node + (size_t)ge * 640 + 256 + 3 * j;
                            float d = xp[0] * ysm[e * 4 + 1] + xp[1] * ysm[e * 4 + 2]
                                    + xp[2] * ysm[e * 4 + 3];
                            v[t] = S3 * d * wsm[e * 68 + kk];
                        }
                    }
                }
                As4[qd] = make_float4(tf32r(v[0]), tf32r(v[1]), tf32r(v[2]), tf32r(v[3]));
            }
            CPA_WAIT1();              // Bp2(q) ready (W2p(next) pends)
            __syncthreads();
#pragma unroll
            for (int ks = 0; ks < 8; ks++) {
                uint32_t a0[4], a1[4];
                ldApk(a0, As4, wm * 2, ks, lane);
                ldApk(a1, As4, wm * 2 + 1, ks, lane);
#pragma unroll
                for (int nt = 0; nt < 4; nt++) {
                    uint32_t b[2];
                    ldBpk(b, Bp2, wn * 4 + nt, ks, lane);
                    mma8(acc[0][nt], a0, b);
                    mma8(acc[1][nt], a1, b);
                }
            }
            __syncthreads();
            if (q < 5) COMMIT_BM2(q + 1);
            else       COMMIT_BM3(0);   // first packed Wv tile flies during epilogue
        }

        // ---- phase-S epilogue: +bias, LN over 256 cols, write ----
        float cbv[8], cgv[8], cBv[8];
#pragma unroll
        for (int nt = 0; nt < 4; nt++)
#pragma unroll
            for (int c = 0; c < 2; c++) {
                int col = wn * 32 + nt * 8 + qc * 2 + c;
                cbv[nt * 2 + c] = bs[col]; cgv[nt * 2 + c] = gs[col]; cBv[nt * 2 + c] = gb[col];
            }
#pragma unroll
        for (int mt = 0; mt < 2; mt++)
#pragma unroll
            for (int h = 0; h < 2; h++) {
                float s = 0.f, q2 = 0.f;
#pragma unroll
                for (int nt = 0; nt < 4; nt++)
#pragma unroll
                    for (int c = 0; c < 2; c++) {
                        float v = acc[mt][nt][h * 2 + c] + cbv[nt * 2 + c];
                        acc[mt][nt][h * 2 + c] = v;
                        s += v; q2 += v * v;
                    }
                s = quad_sum(s); q2 = quad_sum(q2);
                if (qc == 0) {
                    int r = wm * 32 + mt * 16 + qr + h * 8;
                    redS[r * 8 + wn] = s; redQ[r * 8 + wn] = q2;
                }
            }
        __syncthreads();
#pragma unroll
        for (int mt = 0; mt < 2; mt++)
#pragma unroll
            for (int h = 0; h < 2; h++) {
                int r = wm * 32 + mt * 16 + qr + h * 8, ge = e0 + r;
                float s = 0.f, q2 = 0.f;
#pragma unroll
                for (int w8 = 0; w8 < 8; w8++) { s += redS[r * 8 + w8]; q2 += redQ[r * 8 + w8]; }
                float mu = s * (1.f / 256.f);
                float rstd = rsqrtf(fmaxf(q2 * (1.f / 256.f) - mu * mu, 0.f) + EPS);
                if (ge < E) {
#pragma unroll
                    for (int nt = 0; nt < 4; nt++) {
                        int col = wn * 32 + nt * 8 + qc * 2;
                        float2 v;
                        v.x = (acc[mt][nt][h * 2] - mu) * rstd * cgv[nt * 2] + cBv[nt * 2];
                        v.y = (acc[mt][nt][h * 2 + 1] - mu) * rstd * cgv[nt * 2 + 1] + cBv[nt * 2 + 1];
                        *(float2*)&out[(size_t)ge * 640 + col] = v;
                    }
                }
            }
    }

    // ======================= Phase V: vector path ==========================
    {
        const int n0 = wn * 16;
        float accR[2][2][4];
        float accM[3][2][2][4];
#pragma unroll
        for (int mt = 0; mt < 2; mt++)
#pragma unroll
            for (int nt = 0; nt < 2; nt++)
#pragma unroll
                for (int f = 0; f < 4; f++) {
                    accR[mt][nt][f] = 0.f;
#pragma unroll
                    for (int m = 0; m < 3; m++) accM[m][mt][nt][f] = 0.f;
                }

        for (int q = 0; q < 8; q++) {
            CPA_WAIT1();              // W2p(Vq) ready (Bp3(q) may pend)
            __syncthreads();
            int nsl = (q < 7) ? (colbase3(q + 1) >> 6) : -1;
            w_stage(colbase3(q), nsl);
            // build A planes
            if (q < 4) {
                for (int qd = tid; qd < 1024; qd += 512) {
                    int mt = qd >> 8, kg = (qd >> 5) & 7, ln = qd & 31;
                    int ea = mt * 16 + (ln >> 2), ka = kg * 8 + (ln & 3);
                    float v[4];
#pragma unroll
                    for (int t = 0; t < 4; t++) {
                        int e = ea + (t >> 1) * 8, kk = ka + (t & 1) * 4;
                        int ge = e0 + e;
                        v[t] = (ge < E)
                             ? node[(size_t)ge * 640 + q * 64 + kk] * wsm[e * 68 + kk]
                             : 0.f;
                    }
                    As4[qd] = make_float4(tf32r(v[0]), tf32r(v[1]), tf32r(v[2]), tf32r(v[3]));
                }
            } else {
                for (int qd = tid; qd < 1024; qd += 512) {
                    int mt = qd >> 8, kg = (qd >> 5) & 7, ln = qd & 31;
                    int ea = mt * 16 + (ln >> 2), ka = kg * 8 + (ln & 3);
                    float a0[4], a1[4], a2[4];
#pragma unroll
                    for (int t = 0; t < 4; t++) {
                        int e = ea + (t >> 1) * 8, kk = ka + (t & 1) * 4;
                        int ge = e0 + e;
                        a0[t] = a1[t] = a2[t] = 0.f;
                        if (ge < E) {
                            if (q < 6) {
                                int j = (q - 4) * 64 + kk;
                                const float* xp = node + (size_t)ge * 640 + 256 + 3 * j;
                                float f = ysm[e * 4] * wsm[e * 68 + kk];
                                a0[t] = xp[0] * f; a1[t] = xp[1] * f; a2[t] = xp[2] * f;
                            } else {
                                int j = (q - 6) * 64 + kk;
                                const float* xp = node + (size_t)ge * 640 + 256 + 3 * j;
                                float x0v = xp[0], x1v = xp[1], x2v = xp[2];
                                float z0 = ysm[e * 4 + 1], z1 = ysm[e * 4 + 2], z2 = ysm[e * 4 + 3];
                                float f = S2 * wsm[e * 68 + kk];
                                a0[t] = (x1v * z2 - x2v * z1) * f;
                                a1[t] = (x2v * z0 - x0v * z2) * f;
                                a2[t] = (x0v * z1 - x1v * z0) * f;
                            }
                        }
                    }
                    As4[qd] = make_float4(tf32r(a0[0]), tf32r(a0[1]), tf32r(a0[2]), tf32r(a0[3]));
                    A14[qd] = make_float4(tf32r(a1[0]), tf32r(a1[1]), tf32r(a1[2]), tf32r(a1[3]));
                    A24[qd] = make_float4(tf32r(a2[0]), tf32r(a2[1]), tf32r(a2[2]), tf32r(a2[3]));
                }
            }
            if (q < 7) CPA_WAIT1(); else CPA_WAIT0();   // Bp3(q) ready
            __syncthreads();
            if (q < 4) {
#pragma unroll
                for (int ks = 0; ks < 8; ks++) {
                    uint32_t a0[4], a1[4];
                    ldApk(a0, As4, wm * 2, ks, lane);
                    ldApk(a1, As4, wm * 2 + 1, ks, lane);
#pragma unroll
                    for (int nt = 0; nt < 2; nt++) {
                        uint32_t b[2];
                        ldBpk(b, Bp3, wn * 2 + nt, ks, lane);
                        mma8(accR[0][nt], a0, b);
                        mma8(accR[1][nt], a1, b);
                    }
                }
            } else {
#pragma unroll
                for (int ks = 0; ks < 8; ks++) {
                    uint32_t b[2][2];
#pragma unroll
                    for (int nt = 0; nt < 2; nt++) ldBpk(b[nt], Bp3, wn * 2 + nt, ks, lane);
                    const float4* Ap[3] = {As4, A14, A24};
#pragma unroll
                    for (int m = 0; m < 3; m++) {
                        uint32_t a0[4], a1[4];
                        ldApk(a0, Ap[m], wm * 2, ks, lane);
                        ldApk(a1, Ap[m], wm * 2 + 1, ks, lane);
#pragma unroll
                        for (int nt = 0; nt < 2; nt++) {
                            mma8(accM[m][0][nt], a0, b[nt]);
                            mma8(accM[m][1][nt], a1, b[nt]);
                        }
                    }
                }
            }
            __syncthreads();
            if (q < 7) COMMIT_BM3(q + 1);
        }

        // ---- phase-V epilogue: fold R plane, sumsq, norm, write ----
#pragma unroll
        for (int mt = 0; mt < 2; mt++)
#pragma unroll
            for (int h = 0; h < 2; h++) {
                int e = wm * 32 + mt * 16 + qr + h * 8;
                float z0 = ysm[e * 4 + 1], z1 = ysm[e * 4 + 2], z2 = ysm[e * 4 + 3];
                float s = 0.f;
#pragma unroll
                for (int nt = 0; nt < 2; nt++)
#pragma unroll
                    for (int c = 0; c < 2; c++) {
                        float R = accR[mt][nt][h * 2 + c];
                        float v0 = z0 * R + accM[0][mt][nt][h * 2 + c];
                        float v1 = z1 * R + accM[1][mt][nt][h * 2 + c];
                        float v2 = z2 * R + accM[2][mt][nt][h * 2 + c];
                        accM[0][mt][nt][h * 2 + c] = v0;
                        accM[1][mt][nt][h * 2 + c] = v1;
                        accM[2][mt][nt][h * 2 + c] = v2;
                        s += v0 * v0 + v1 * v1 + v2 * v2;
                    }
                s = quad_sum(s);
                if (qc == 0) redQ[e * 8 + wn] = s;
            }
        __syncthreads();
        float cg[4];
#pragma unroll
        for (int nt = 0; nt < 2; nt++)
#pragma unroll
            for (int c = 0; c < 2; c++) cg[nt * 2 + c] = gv[n0 + nt * 8 + qc * 2 + c];
#pragma unroll
        for (int mt = 0; mt < 2; mt++)
#pragma unroll
            for (int h = 0; h < 2; h++) {
                int e = wm * 32 + mt * 16 + qr + h * 8, ge = e0 + e;
                float qt = 0.f;
#pragma unroll
                for (int w8 = 0; w8 < 8; w8++) qt += redQ[e * 8 + w8];
                float rstd = rsqrtf(qt * (1.f / 384.f) + EPS);
                if (ge < E) {
                    float* ob = out + (size_t)ge * 640 + 256;
#pragma unroll
                    for (int nt = 0; nt < 2; nt++)
#pragma unroll
                        for (int c = 0; c < 2; c++) {
                            int col = n0 + nt * 8 + qc * 2 + c;
                            float g = cg[nt * 2 + c] * rstd;
                            ob[3 * col + 0] = accM[0][mt][nt][h * 2 + c] * g;
                            ob[3 * col + 1] = accM[1][mt][nt][h * 2 + c] * g;
                            ob[3 * col + 2] = accM[2][mt][nt][h * 2 + c] * g;
                        }
                }
            }
    }
#undef COMMIT_BM2
#undef COMMIT_BM3
}

// ---------------------------------------------------------------------------
extern "C" void kernel_launch(void* const* d_in, const int* in_sizes, int n_in,
                              void* d_out, int out_size)
{
    const float* node  = (const float*)d_in[0];   // (E, 640)
    const float* eattr = (const float*)d_in[1];   // (E, 4)
    const float* escal = (const float*)d_in[2];   // (E, 64)
    const float* rW1   = (const float*)d_in[3];   // (64, 64)
    const float* rb1   = (const float*)d_in[4];   // (64,)
    const float* rlg   = (const float*)d_in[5];   // (64,)
    const float* rlb   = (const float*)d_in[6];   // (64,)
    const float* rW2   = (const float*)d_in[7];   // (64, 896)
    const float* roff  = (const float*)d_in[8];   // (896,)
    const float* Ws    = (const float*)d_in[9];   // (384, 256)
    const float* bs    = (const float*)d_in[10];  // (256,)
    const float* Wv    = (const float*)d_in[11];  // (512, 128)
    const float* gs    = (const float*)d_in[12];  // (256,)
    const float* gb    = (const float*)d_in[13];  // (256,)
    const float* gv    = (const float*)d_in[14];  // (128,)
    float* out = (float*)d_out;

    const int E = in_sizes[1] / 4;
    const int nb64 = (E + 63) / 64;

    cudaFuncSetAttribute(ff, cudaFuncAttributeMaxDynamicSharedMemorySize, FF_SMEM);

    k0_pack<<<440, 256>>>(rW1, rW2, Ws, Wv);
    ff<<<nb64, 512, FF_SMEM>>>(node, eattr, escal, rb1, rlg, rlb, roff,
                               bs, gs, gb, gv, out, E);
}